// round 1
// baseline (speedup 1.0000x reference)
#include <cuda_runtime.h>

#define PP 8
#define NN 1024
#define DD 768
#define HH 12
#define HSZ 64

// ---- scratch (static: no allocations allowed) ----
__device__ float gQ[PP*HH*NN*HSZ];
__device__ float gK[PP*HH*NN*HSZ];
__device__ float gV[PP*HH*NN*HSZ];
__device__ float gCtx[PP*NN*DD];
__device__ float gMV[PP*HH*HSZ];   // sum_k mask[p,k] * V[p,h,k,:]  (post-softmax mask term)

// ============================================================
// GEMM 1: QKV projection.  C[8192,2304] = X[8192,768] @ W + b,
// scattered into gQ/gK/gV with layout [p][h][n][hs].
// 128x128x8 tile, 256 threads, 8x8 register tile per thread.
// ============================================================
__global__ __launch_bounds__(256) void qkv_gemm(const float* __restrict__ X,
                                                const float* __restrict__ W,
                                                const float* __restrict__ B) {
    __shared__ float Ast[8][132];   // [k][m], pad 4 -> conflict-free scatter writes
    __shared__ float Bs [8][132];   // [k][n]
    int tid = threadIdx.x;
    int tx = tid & 15, ty = tid >> 4;
    int row0 = blockIdx.y * 128, col0 = blockIdx.x * 128;

    float acc[8][8];
    #pragma unroll
    for (int i = 0; i < 8; i++)
        #pragma unroll
        for (int j = 0; j < 8; j++) acc[i][j] = 0.f;

    int a_r = tid >> 1, a_c = (tid & 1) << 2;
    int b_r = tid >> 5, b_c = (tid & 31) << 2;
    const float* Aptr = X + (size_t)(row0 + a_r) * DD + a_c;
    const float* Bptr = W + (size_t)b_r * (3*DD) + col0 + b_c;

    for (int k0 = 0; k0 < DD; k0 += 8) {
        float4 av = *(const float4*)(Aptr + k0);
        float4 bv = *(const float4*)(Bptr + (size_t)k0 * (3*DD));
        __syncthreads();
        Ast[a_c+0][a_r] = av.x; Ast[a_c+1][a_r] = av.y;
        Ast[a_c+2][a_r] = av.z; Ast[a_c+3][a_r] = av.w;
        *(float4*)&Bs[b_r][b_c] = bv;
        __syncthreads();
        #pragma unroll
        for (int kk = 0; kk < 8; kk++) {
            float a[8], b[8];
            *(float4*)&a[0] = *(float4*)&Ast[kk][ty*8];
            *(float4*)&a[4] = *(float4*)&Ast[kk][ty*8+4];
            *(float4*)&b[0] = *(float4*)&Bs[kk][tx*8];
            *(float4*)&b[4] = *(float4*)&Bs[kk][tx*8+4];
            #pragma unroll
            for (int i = 0; i < 8; i++)
                #pragma unroll
                for (int j = 0; j < 8; j++) acc[i][j] += a[i] * b[j];
        }
    }

    // epilogue: add bias, scatter into Q/K/V [p][h][n][hs]
    #pragma unroll
    for (int i = 0; i < 8; i++) {
        int m = row0 + ty*8 + i;
        int p = m >> 10, n = m & 1023;
        #pragma unroll
        for (int j = 0; j < 8; j++) {
            int nc = col0 + tx*8 + j;
            float v = acc[i][j] + B[nc];
            int which = nc / DD;
            int rem   = nc - which * DD;
            int h  = rem >> 6, hs = rem & 63;
            float* dst = (which == 0) ? gQ : ((which == 1) ? gK : gV);
            dst[(((size_t)(p*HH + h) << 10) + n) * HSZ + hs] = v;
        }
    }
}

// ============================================================
// Post-softmax mask term: gMV[p,h,hs] = sum_k mask[p,k] * V[p,h,k,hs]
// ============================================================
__global__ void maskv_kernel(const float* __restrict__ mask) {
    int ph = blockIdx.x;           // 0..95
    int p  = ph / HH;
    int hs = threadIdx.x;          // 0..63
    const float* Vp = gV + (size_t)ph * NN * HSZ;
    const float* mp = mask + (size_t)p * NN;
    float acc = 0.f;
    for (int k = 0; k < NN; k++) acc += mp[k] * Vp[(size_t)k * HSZ + hs];
    gMV[ph * HSZ + hs] = acc;
}

// ============================================================
// Flash-style attention. One CTA = (p, h, 32-query block).
// 128 threads = 8(ty) x 16(tx); each thread owns a 4x4 tile of
// the 32x64 S block and a 4x4 tile of the 32x64 O accumulator.
// smem: Qs row-major, Kt transposed [hs][c], Vs row-major,
// Ps (probs) row-major aliased onto Kt storage.
// ============================================================
__global__ __launch_bounds__(128) void attn_kernel() {
    __shared__ __align__(16) float Qs [32*68];
    __shared__ __align__(16) float KPs[64*68];   // Kt, later reused as Ps[32][68]
    __shared__ __align__(16) float Vs [64*68];

    int qb = blockIdx.x, h = blockIdx.y, p = blockIdx.z;
    int ph = p * HH + h;
    const float* Qg = gQ + ((size_t)ph * NN + qb*32) * HSZ;
    const float* Kg = gK + (size_t)ph * NN * HSZ;
    const float* Vg = gV + (size_t)ph * NN * HSZ;

    int tid = threadIdx.x;
    int tx = tid & 15, ty = tid >> 4;
    int r0 = ty * 4, c0 = tx * 4;

    // load Q block (row-major, float4, conflict-free)
    for (int idx = tid; idx < 32*16; idx += 128) {
        int r = idx >> 4, s = (idx & 15) << 2;
        *(float4*)&Qs[r*68 + s] = *(const float4*)&Qg[(size_t)r*HSZ + s];
    }

    float m_i[4], l_i[4], O[4][4];
    #pragma unroll
    for (int i = 0; i < 4; i++) {
        m_i[i] = -1e30f; l_i[i] = 0.f;
        #pragma unroll
        for (int j = 0; j < 4; j++) O[i][j] = 0.f;
    }

    for (int kb = 0; kb < 16; kb++) {
        __syncthreads();   // prev-iter Ps/Vs reads done (Ps aliases Kt)

        // K tile transposed: Kt[hs][c] (coalesced global reads, ~4-way STS)
        for (int idx = tid; idx < 64*64; idx += 128) {
            int c = idx >> 6, hs = idx & 63;
            KPs[hs*68 + c] = Kg[((size_t)(kb*64 + c)) * HSZ + hs];
        }
        // V tile row-major (float4 both sides, conflict-free)
        for (int idx = tid; idx < 64*16; idx += 128) {
            int c = idx >> 4, s = (idx & 15) << 2;
            *(float4*)&Vs[c*68 + s] = *(const float4*)&Vg[((size_t)(kb*64 + c)) * HSZ + s];
        }
        __syncthreads();

        // S = Q @ K^T  (32x64), scale by sqrt(HS)=8
        float S[4][4];
        #pragma unroll
        for (int i = 0; i < 4; i++)
            #pragma unroll
            for (int j = 0; j < 4; j++) S[i][j] = 0.f;
        #pragma unroll 16
        for (int kk = 0; kk < 64; kk++) {
            float4 b = *(float4*)&KPs[kk*68 + c0];
            float a0 = Qs[(r0+0)*68 + kk];
            float a1 = Qs[(r0+1)*68 + kk];
            float a2 = Qs[(r0+2)*68 + kk];
            float a3 = Qs[(r0+3)*68 + kk];
            S[0][0] += a0*b.x; S[0][1] += a0*b.y; S[0][2] += a0*b.z; S[0][3] += a0*b.w;
            S[1][0] += a1*b.x; S[1][1] += a1*b.y; S[1][2] += a1*b.z; S[1][3] += a1*b.w;
            S[2][0] += a2*b.x; S[2][1] += a2*b.y; S[2][2] += a2*b.z; S[2][3] += a2*b.w;
            S[3][0] += a3*b.x; S[3][1] += a3*b.y; S[3][2] += a3*b.z; S[3][3] += a3*b.w;
        }
        #pragma unroll
        for (int i = 0; i < 4; i++)
            #pragma unroll
            for (int j = 0; j < 4; j++) S[i][j] *= 8.0f;

        // online softmax: row reductions across the 16 tx lanes (same warp half)
        #pragma unroll
        for (int i = 0; i < 4; i++) {
            float rm = fmaxf(fmaxf(S[i][0], S[i][1]), fmaxf(S[i][2], S[i][3]));
            rm = fmaxf(rm, __shfl_xor_sync(0xffffffffu, rm, 8));
            rm = fmaxf(rm, __shfl_xor_sync(0xffffffffu, rm, 4));
            rm = fmaxf(rm, __shfl_xor_sync(0xffffffffu, rm, 2));
            rm = fmaxf(rm, __shfl_xor_sync(0xffffffffu, rm, 1));
            float mn = fmaxf(m_i[i], rm);
            float corr = __expf(m_i[i] - mn);
            m_i[i] = mn;
            float rs = 0.f;
            #pragma unroll
            for (int j = 0; j < 4; j++) {
                float e = __expf(S[i][j] - mn);
                S[i][j] = e; rs += e;
            }
            rs += __shfl_xor_sync(0xffffffffu, rs, 8);
            rs += __shfl_xor_sync(0xffffffffu, rs, 4);
            rs += __shfl_xor_sync(0xffffffffu, rs, 2);
            rs += __shfl_xor_sync(0xffffffffu, rs, 1);
            l_i[i] = l_i[i] * corr + rs;
            #pragma unroll
            for (int j = 0; j < 4; j++) O[i][j] *= corr;
        }

        __syncthreads();   // all warps done reading Kt
        // write probs row-major into the Kt storage (float4, conflict-free)
        #pragma unroll
        for (int i = 0; i < 4; i++)
            *(float4*)&KPs[(r0+i)*68 + c0] = make_float4(S[i][0], S[i][1], S[i][2], S[i][3]);
        __syncthreads();

        // O += P @ V  (32x64 += 32x64 @ 64x64)
        #pragma unroll 8
        for (int c = 0; c < 64; c++) {
            float4 v = *(float4*)&Vs[c*68 + c0];
            float p0 = KPs[(r0+0)*68 + c];
            float p1 = KPs[(r0+1)*68 + c];
            float p2 = KPs[(r0+2)*68 + c];
            float p3 = KPs[(r0+3)*68 + c];
            O[0][0] += p0*v.x; O[0][1] += p0*v.y; O[0][2] += p0*v.z; O[0][3] += p0*v.w;
            O[1][0] += p1*v.x; O[1][1] += p1*v.y; O[1][2] += p1*v.z; O[1][3] += p1*v.w;
            O[2][0] += p2*v.x; O[2][1] += p2*v.y; O[2][2] += p2*v.z; O[2][3] += p2*v.w;
            O[3][0] += p3*v.x; O[3][1] += p3*v.y; O[3][2] += p3*v.z; O[3][3] += p3*v.w;
        }
    }

    // epilogue: ctx[p, q, h*64+hs] = O/l + maskV term
    float4 mv = *(float4*)&gMV[ph*HSZ + c0];
    #pragma unroll
    for (int i = 0; i < 4; i++) {
        float inv = 1.0f / l_i[i];
        int q = qb*32 + r0 + i;
        float4 o;
        o.x = O[i][0]*inv + mv.x;
        o.y = O[i][1]*inv + mv.y;
        o.z = O[i][2]*inv + mv.z;
        o.w = O[i][3]*inv + mv.w;
        *(float4*)&gCtx[((size_t)p*NN + q) * DD + h*HSZ + c0] = o;
    }
}

// ============================================================
// GEMM 2: output projection. out[8192,768] = ctx @ W + b
// ============================================================
__global__ __launch_bounds__(256) void proj_gemm(const float* __restrict__ Wp,
                                                 const float* __restrict__ Bp,
                                                 float* __restrict__ out) {
    __shared__ float Ast[8][132];
    __shared__ float Bs [8][132];
    int tid = threadIdx.x;
    int tx = tid & 15, ty = tid >> 4;
    int row0 = blockIdx.y * 128, col0 = blockIdx.x * 128;

    float acc[8][8];
    #pragma unroll
    for (int i = 0; i < 8; i++)
        #pragma unroll
        for (int j = 0; j < 8; j++) acc[i][j] = 0.f;

    int a_r = tid >> 1, a_c = (tid & 1) << 2;
    int b_r = tid >> 5, b_c = (tid & 31) << 2;
    const float* Aptr = gCtx + (size_t)(row0 + a_r) * DD + a_c;
    const float* Bptr = Wp + (size_t)b_r * DD + col0 + b_c;

    for (int k0 = 0; k0 < DD; k0 += 8) {
        float4 av = *(const float4*)(Aptr + k0);
        float4 bv = *(const float4*)(Bptr + (size_t)k0 * DD);
        __syncthreads();
        Ast[a_c+0][a_r] = av.x; Ast[a_c+1][a_r] = av.y;
        Ast[a_c+2][a_r] = av.z; Ast[a_c+3][a_r] = av.w;
        *(float4*)&Bs[b_r][b_c] = bv;
        __syncthreads();
        #pragma unroll
        for (int kk = 0; kk < 8; kk++) {
            float a[8], b[8];
            *(float4*)&a[0] = *(float4*)&Ast[kk][ty*8];
            *(float4*)&a[4] = *(float4*)&Ast[kk][ty*8+4];
            *(float4*)&b[0] = *(float4*)&Bs[kk][tx*8];
            *(float4*)&b[4] = *(float4*)&Bs[kk][tx*8+4];
            #pragma unroll
            for (int i = 0; i < 8; i++)
                #pragma unroll
                for (int j = 0; j < 8; j++) acc[i][j] += a[i] * b[j];
        }
    }

    float4 bb0 = *(const float4*)&Bp[col0 + tx*8];
    float4 bb1 = *(const float4*)&Bp[col0 + tx*8 + 4];
    #pragma unroll
    for (int i = 0; i < 8; i++) {
        int m = row0 + ty*8 + i;
        float* op = out + (size_t)m * DD + col0 + tx*8;
        float4 o0, o1;
        o0.x = acc[i][0] + bb0.x; o0.y = acc[i][1] + bb0.y;
        o0.z = acc[i][2] + bb0.z; o0.w = acc[i][3] + bb0.w;
        o1.x = acc[i][4] + bb1.x; o1.y = acc[i][5] + bb1.y;
        o1.z = acc[i][6] + bb1.z; o1.w = acc[i][7] + bb1.w;
        *(float4*)op       = o0;
        *(float4*)(op + 4) = o1;
    }
}

extern "C" void kernel_launch(void* const* d_in, const int* in_sizes, int n_in,
                              void* d_out, int out_size) {
    const float* X      = (const float*)d_in[0];  // pixel_values [8,1024,768]
    const float* mask   = (const float*)d_in[1];  // attention_mask [8,1,1,1024]
    const float* qkv_w  = (const float*)d_in[2];  // [768, 2304]
    const float* qkv_b  = (const float*)d_in[3];  // [2304]
    const float* proj_w = (const float*)d_in[4];  // [768, 768]
    const float* proj_b = (const float*)d_in[5];  // [768]
    float* out = (float*)d_out;                   // [8,1024,768]

    qkv_gemm<<<dim3(3*DD/128, PP*NN/128), 256>>>(X, qkv_w, qkv_b);
    maskv_kernel<<<PP*HH, HSZ>>>(mask);
    attn_kernel<<<dim3(NN/32, HH, PP), 128>>>();
    proj_gemm<<<dim3(DD/128, PP*NN/128), 256>>>(proj_w, proj_b, out);
}

// round 3
// speedup vs baseline: 1.3871x; 1.3871x over previous
#include <cuda_runtime.h>
#include <cuda_bf16.h>
#include <cstdint>

#define PP 8
#define NN 1024
#define DD 768
#define HH 12
#define HSZ 64

// ---- scratch (static: no allocations allowed) ----
__device__ float gQ[PP*HH*NN*HSZ];
__device__ float gK[PP*HH*NN*HSZ];
__device__ float gV[PP*HH*NN*HSZ];
__device__ float gMV[PP*HH*HSZ];
__device__ __nv_bfloat16 gXhi[PP*NN*DD];
__device__ __nv_bfloat16 gXlo[PP*NN*DD];
__device__ __nv_bfloat16 gWqh[3*DD*DD];   // qkv_w transposed: [2304][768]
__device__ __nv_bfloat16 gWql[3*DD*DD];
__device__ __nv_bfloat16 gWph[DD*DD];     // proj_w transposed: [768][768]
__device__ __nv_bfloat16 gWpl[DD*DD];
__device__ __nv_bfloat16 gCh[PP*NN*DD];   // ctx hi/lo
__device__ __nv_bfloat16 gCl[PP*NN*DD];

// ================= helpers =================
__device__ __forceinline__ uint32_t smem_u32(const void* p) {
    uint32_t a;
    asm("{ .reg .u64 t; cvta.to.shared.u64 t, %1; cvt.u32.u64 %0, t; }" : "=r"(a) : "l"(p));
    return a;
}
__device__ __forceinline__ uint32_t lds32(uint32_t a) {
    uint32_t v;
    asm volatile("ld.shared.b32 %0, [%1];" : "=r"(v) : "r"(a));
    return v;
}
#define CP16(saddr, gptr) \
    asm volatile("cp.async.cg.shared.global [%0], [%1], 16;" :: "r"(saddr), "l"(gptr))
#define CP_COMMIT() asm volatile("cp.async.commit_group;" ::: "memory")
#define CP_WAIT1()  asm volatile("cp.async.wait_group 1;" ::: "memory")
#define CP_WAIT0()  asm volatile("cp.async.wait_group 0;" ::: "memory")

__device__ __forceinline__ void mma16816(float* c, const uint32_t* a, const uint32_t* b) {
    asm volatile("mma.sync.aligned.m16n8k16.row.col.f32.bf16.bf16.f32 "
                 "{%0,%1,%2,%3}, {%4,%5,%6,%7}, {%8,%9}, {%0,%1,%2,%3};"
                 : "+f"(c[0]), "+f"(c[1]), "+f"(c[2]), "+f"(c[3])
                 : "r"(a[0]), "r"(a[1]), "r"(a[2]), "r"(a[3]), "r"(b[0]), "r"(b[1]));
}

// ================= split / transpose-split =================
__global__ void split_kernel(const float* __restrict__ src,
                             __nv_bfloat16* __restrict__ hi,
                             __nv_bfloat16* __restrict__ lo, int n4) {
    int i = blockIdx.x * blockDim.x + threadIdx.x;
    if (i >= n4) return;
    float4 v = ((const float4*)src)[i];
    __nv_bfloat16 h[4], l[4];
    float x[4] = {v.x, v.y, v.z, v.w};
    #pragma unroll
    for (int j = 0; j < 4; j++) {
        h[j] = __float2bfloat16_rn(x[j]);
        l[j] = __float2bfloat16_rn(x[j] - __bfloat162float(h[j]));
    }
    ((uint2*)hi)[i] = *(uint2*)h;
    ((uint2*)lo)[i] = *(uint2*)l;
}

// W[K][N] -> T[N][K] with hi/lo split
__global__ void tsplit_kernel(const float* __restrict__ W,
                              __nv_bfloat16* __restrict__ Th,
                              __nv_bfloat16* __restrict__ Tl, int K, int N) {
    __shared__ float t[32][33];
    int k0 = blockIdx.y * 32, n0 = blockIdx.x * 32;
    int tx = threadIdx.x, ty = threadIdx.y;
    #pragma unroll
    for (int i = 0; i < 4; i++)
        t[ty + 8*i][tx] = W[(size_t)(k0 + ty + 8*i) * N + n0 + tx];
    __syncthreads();
    #pragma unroll
    for (int i = 0; i < 4; i++) {
        float x = t[tx][ty + 8*i];
        __nv_bfloat16 h = __float2bfloat16_rn(x);
        __nv_bfloat16 l = __float2bfloat16_rn(x - __bfloat162float(h));
        size_t o = (size_t)(n0 + ty + 8*i) * K + k0 + tx;
        Th[o] = h; Tl[o] = l;
    }
}

// ================= bf16x3 GEMM via mma.sync (HMMA) =================
// C[8192, Ntot] = A[8192,768] @ T^T (+bias).
// CTA tile 128(m) x 128(n), K-chunk 32, 8 warps (warp tile 32m x 64n),
// double-buffered smem via cp.async.
// Buffer layout (bf16 units, per buffer): Ah[128][40], Al, Bh[128][40], Bl.
#define PADK 40
#define TILE_E (128*PADK)            // 5120 bf16 per tile
#define BUF_BYTES (4*TILE_E*2)       // 40960 B
#define GEMM_SMEM (2*BUF_BYTES)      // 81920 B

__global__ __launch_bounds__(256, 1) void gemm_mma(int mode,
                                                   const float* __restrict__ bias,
                                                   float* __restrict__ out) {
    extern __shared__ __align__(16) char smem[];
    uint32_t sb = smem_u32(smem);
    int tid = threadIdx.x, wid = tid >> 5, lane = tid & 31;
    int wm = wid & 3, wn = wid >> 2;
    int row0 = blockIdx.y * 128, col0 = blockIdx.x * 128;
    int gid = lane >> 2, tig = lane & 3;

    const __nv_bfloat16* Ah = mode ? gCh : gXhi;
    const __nv_bfloat16* Al = mode ? gCl : gXlo;
    const __nv_bfloat16* Bh = mode ? gWph : gWqh;
    const __nv_bfloat16* Bl = mode ? gWpl : gWql;
    const __nv_bfloat16* srcs[4] = {Ah, Al, Bh, Bl};

    float acc[2][8][4];
    #pragma unroll
    for (int i = 0; i < 2; i++)
        #pragma unroll
        for (int j = 0; j < 8; j++)
            #pragma unroll
            for (int q = 0; q < 4; q++) acc[i][j][q] = 0.f;

    // ---- fill chunk c into buffer s ----
    auto fill = [&](int s, int c) {
        int k0 = c * 32;
        uint32_t sbase = sb + s * BUF_BYTES;
        #pragma unroll
        for (int t = 0; t < 4; t++) {
            const __nv_bfloat16* src = srcs[t];
            int rbase = (t < 2) ? row0 : col0;
            #pragma unroll
            for (int j = 0; j < 2; j++) {
                int e = j * 256 + tid;          // 0..511
                int r = e >> 2, v = e & 3;
                uint32_t daddr = sbase + (uint32_t)(t * TILE_E + r * PADK + v * 8) * 2;
                const __nv_bfloat16* g = src + (size_t)(rbase + r) * DD + k0 + v * 8;
                CP16(daddr, g);
            }
        }
        CP_COMMIT();
    };

    fill(0, 0);
    for (int c = 0; c < 24; c++) {
        if (c < 23) fill((c + 1) & 1, c + 1);
        if (c < 23) CP_WAIT1(); else CP_WAIT0();
        __syncthreads();

        uint32_t base = sb + (c & 1) * BUF_BYTES;
        uint32_t Ahb = base, Alb = base + TILE_E*2;
        uint32_t Bhb = base + 2*TILE_E*2, Blb = base + 3*TILE_E*2;

        #pragma unroll
        for (int ks = 0; ks < 2; ks++) {
            int kcol = ks * 16 + tig * 2;      // bf16 col within chunk
            uint32_t ah[2][4], al[2][4];
            #pragma unroll
            for (int mt = 0; mt < 2; mt++) {
                int r = wm * 32 + mt * 16 + gid;
                uint32_t o = (uint32_t)(r * PADK + kcol) * 2;
                ah[mt][0] = lds32(Ahb + o);
                ah[mt][1] = lds32(Ahb + o + 8*PADK*2);
                ah[mt][2] = lds32(Ahb + o + 16);
                ah[mt][3] = lds32(Ahb + o + 8*PADK*2 + 16);
                al[mt][0] = lds32(Alb + o);
                al[mt][1] = lds32(Alb + o + 8*PADK*2);
                al[mt][2] = lds32(Alb + o + 16);
                al[mt][3] = lds32(Alb + o + 8*PADK*2 + 16);
            }
            #pragma unroll
            for (int half = 0; half < 2; half++) {
                uint32_t bh[4][2], bl[4][2];
                #pragma unroll
                for (int nt = 0; nt < 4; nt++) {
                    int n = wn * 64 + half * 32 + nt * 8 + gid;
                    uint32_t o = (uint32_t)(n * PADK + kcol) * 2;
                    bh[nt][0] = lds32(Bhb + o);
                    bh[nt][1] = lds32(Bhb + o + 16);
                    bl[nt][0] = lds32(Blb + o);
                    bl[nt][1] = lds32(Blb + o + 16);
                }
                #pragma unroll
                for (int mt = 0; mt < 2; mt++)
                    #pragma unroll
                    for (int nt = 0; nt < 4; nt++) {
                        float* cc = acc[mt][half * 4 + nt];
                        mma16816(cc, ah[mt], bh[nt]);
                        mma16816(cc, ah[mt], bl[nt]);
                        mma16816(cc, al[mt], bh[nt]);
                    }
            }
        }
        __syncthreads();
    }

    // ---- epilogue ----
    #pragma unroll
    for (int mt = 0; mt < 2; mt++) {
        int m_lo = row0 + wm * 32 + mt * 16 + gid;
        int m_hi = m_lo + 8;
        #pragma unroll
        for (int j = 0; j < 8; j++) {
            int nc = col0 + wn * 64 + (j >> 2) * 32 + (j & 3) * 8 + tig * 2;
            float b0 = bias[nc], b1 = bias[nc + 1];
            float* cc = acc[mt][j];
            if (mode == 0) {
                int which = (nc >= 2*DD) ? 2 : ((nc >= DD) ? 1 : 0);
                int rem = nc - which * DD;
                int h = rem >> 6, hs = rem & 63;
                float* dst = (which == 0) ? gQ : ((which == 1) ? gK : gV);
                {
                    int p = m_lo >> 10, n = m_lo & 1023;
                    float2 v = make_float2(cc[0] + b0, cc[1] + b1);
                    *(float2*)&dst[(((size_t)(p*HH + h) << 10) + n) * HSZ + hs] = v;
                }
                {
                    int p = m_hi >> 10, n = m_hi & 1023;
                    float2 v = make_float2(cc[2] + b0, cc[3] + b1);
                    *(float2*)&dst[(((size_t)(p*HH + h) << 10) + n) * HSZ + hs] = v;
                }
            } else {
                *(float2*)&out[(size_t)m_lo * DD + nc] = make_float2(cc[0] + b0, cc[1] + b1);
                *(float2*)&out[(size_t)m_hi * DD + nc] = make_float2(cc[2] + b0, cc[3] + b1);
            }
        }
    }
}

// ================= post-softmax mask term =================
__global__ void maskv_kernel(const float* __restrict__ mask) {
    __shared__ float red[256];
    int ph = blockIdx.x;
    int p = ph / HH;
    int t = threadIdx.x;
    int hs = t & 63, ks = t >> 6;
    const float* Vp = gV + (size_t)ph * NN * HSZ;
    const float* mp = mask + (size_t)p * NN;
    float acc = 0.f;
    for (int k = ks; k < NN; k += 4) acc += mp[k] * Vp[(size_t)k * HSZ + hs];
    red[t] = acc;
    __syncthreads();
    if (t < 128) red[t] += red[t + 128];
    __syncthreads();
    if (t < 64) gMV[ph * HSZ + t] = red[t] + red[t + 64];
}

// ================= flash attention (fp32 SIMT) =================
__global__ __launch_bounds__(128) void attn_kernel() {
    __shared__ __align__(16) float Qs [32*68];
    __shared__ __align__(16) float KPs[64*68];
    __shared__ __align__(16) float Vs [64*68];

    int qb = blockIdx.x, h = blockIdx.y, p = blockIdx.z;
    int ph = p * HH + h;
    const float* Qg = gQ + ((size_t)ph * NN + qb*32) * HSZ;
    const float* Kg = gK + (size_t)ph * NN * HSZ;
    const float* Vg = gV + (size_t)ph * NN * HSZ;

    int tid = threadIdx.x;
    int tx = tid & 15, ty = tid >> 4;
    int r0 = ty * 4, c0 = tx * 4;

    for (int idx = tid; idx < 32*16; idx += 128) {
        int r = idx >> 4, s = (idx & 15) << 2;
        *(float4*)&Qs[r*68 + s] = *(const float4*)&Qg[(size_t)r*HSZ + s];
    }

    float m_i[4], l_i[4], O[4][4];
    #pragma unroll
    for (int i = 0; i < 4; i++) {
        m_i[i] = -1e30f; l_i[i] = 0.f;
        #pragma unroll
        for (int j = 0; j < 4; j++) O[i][j] = 0.f;
    }

    for (int kb = 0; kb < 16; kb++) {
        __syncthreads();
        for (int idx = tid; idx < 64*64; idx += 128) {
            int c = idx >> 6, hs = idx & 63;
            KPs[hs*68 + c] = Kg[((size_t)(kb*64 + c)) * HSZ + hs];
        }
        for (int idx = tid; idx < 64*16; idx += 128) {
            int c = idx >> 4, s = (idx & 15) << 2;
            *(float4*)&Vs[c*68 + s] = *(const float4*)&Vg[((size_t)(kb*64 + c)) * HSZ + s];
        }
        __syncthreads();

        float S[4][4];
        #pragma unroll
        for (int i = 0; i < 4; i++)
            #pragma unroll
            for (int j = 0; j < 4; j++) S[i][j] = 0.f;
        #pragma unroll 16
        for (int kk = 0; kk < 64; kk++) {
            float4 b = *(float4*)&KPs[kk*68 + c0];
            float a0 = Qs[(r0+0)*68 + kk];
            float a1 = Qs[(r0+1)*68 + kk];
            float a2 = Qs[(r0+2)*68 + kk];
            float a3 = Qs[(r0+3)*68 + kk];
            S[0][0] += a0*b.x; S[0][1] += a0*b.y; S[0][2] += a0*b.z; S[0][3] += a0*b.w;
            S[1][0] += a1*b.x; S[1][1] += a1*b.y; S[1][2] += a1*b.z; S[1][3] += a1*b.w;
            S[2][0] += a2*b.x; S[2][1] += a2*b.y; S[2][2] += a2*b.z; S[2][3] += a2*b.w;
            S[3][0] += a3*b.x; S[3][1] += a3*b.y; S[3][2] += a3*b.z; S[3][3] += a3*b.w;
        }
        #pragma unroll
        for (int i = 0; i < 4; i++)
            #pragma unroll
            for (int j = 0; j < 4; j++) S[i][j] *= 8.0f;

        #pragma unroll
        for (int i = 0; i < 4; i++) {
            float rm = fmaxf(fmaxf(S[i][0], S[i][1]), fmaxf(S[i][2], S[i][3]));
            rm = fmaxf(rm, __shfl_xor_sync(0xffffffffu, rm, 8));
            rm = fmaxf(rm, __shfl_xor_sync(0xffffffffu, rm, 4));
            rm = fmaxf(rm, __shfl_xor_sync(0xffffffffu, rm, 2));
            rm = fmaxf(rm, __shfl_xor_sync(0xffffffffu, rm, 1));
            float mn = fmaxf(m_i[i], rm);
            float corr = __expf(m_i[i] - mn);
            m_i[i] = mn;
            float rs = 0.f;
            #pragma unroll
            for (int j = 0; j < 4; j++) {
                float e = __expf(S[i][j] - mn);
                S[i][j] = e; rs += e;
            }
            rs += __shfl_xor_sync(0xffffffffu, rs, 8);
            rs += __shfl_xor_sync(0xffffffffu, rs, 4);
            rs += __shfl_xor_sync(0xffffffffu, rs, 2);
            rs += __shfl_xor_sync(0xffffffffu, rs, 1);
            l_i[i] = l_i[i] * corr + rs;
            #pragma unroll
            for (int j = 0; j < 4; j++) O[i][j] *= corr;
        }

        __syncthreads();
        #pragma unroll
        for (int i = 0; i < 4; i++)
            *(float4*)&KPs[(r0+i)*68 + c0] = make_float4(S[i][0], S[i][1], S[i][2], S[i][3]);
        __syncthreads();

        #pragma unroll 8
        for (int c = 0; c < 64; c++) {
            float4 v = *(float4*)&Vs[c*68 + c0];
            float p0 = KPs[(r0+0)*68 + c];
            float p1 = KPs[(r0+1)*68 + c];
            float p2 = KPs[(r0+2)*68 + c];
            float p3 = KPs[(r0+3)*68 + c];
            O[0][0] += p0*v.x; O[0][1] += p0*v.y; O[0][2] += p0*v.z; O[0][3] += p0*v.w;
            O[1][0] += p1*v.x; O[1][1] += p1*v.y; O[1][2] += p1*v.z; O[1][3] += p1*v.w;
            O[2][0] += p2*v.x; O[2][1] += p2*v.y; O[2][2] += p2*v.z; O[2][3] += p2*v.w;
            O[3][0] += p3*v.x; O[3][1] += p3*v.y; O[3][2] += p3*v.z; O[3][3] += p3*v.w;
        }
    }

    // epilogue: ctx as bf16 hi/lo
    float4 mv = *(float4*)&gMV[ph*HSZ + c0];
    #pragma unroll
    for (int i = 0; i < 4; i++) {
        float inv = 1.0f / l_i[i];
        int q = qb*32 + r0 + i;
        float o[4];
        o[0] = O[i][0]*inv + mv.x;
        o[1] = O[i][1]*inv + mv.y;
        o[2] = O[i][2]*inv + mv.z;
        o[3] = O[i][3]*inv + mv.w;
        size_t base = ((size_t)p*NN + q) * DD + h*HSZ + c0;
        __nv_bfloat16 hb[4], lb[4];
        #pragma unroll
        for (int j = 0; j < 4; j++) {
            hb[j] = __float2bfloat16_rn(o[j]);
            lb[j] = __float2bfloat16_rn(o[j] - __bfloat162float(hb[j]));
        }
        *(uint2*)&gCh[base] = *(uint2*)hb;
        *(uint2*)&gCl[base] = *(uint2*)lb;
    }
}

extern "C" void kernel_launch(void* const* d_in, const int* in_sizes, int n_in,
                              void* d_out, int out_size) {
    const float* X      = (const float*)d_in[0];
    const float* mask   = (const float*)d_in[1];
    const float* qkv_w  = (const float*)d_in[2];
    const float* qkv_b  = (const float*)d_in[3];
    const float* proj_w = (const float*)d_in[4];
    const float* proj_b = (const float*)d_in[5];
    float* out = (float*)d_out;

    cudaFuncSetAttribute(gemm_mma, cudaFuncAttributeMaxDynamicSharedMemorySize, GEMM_SMEM);

    __nv_bfloat16 *xhi, *xlo, *wqh, *wql, *wph, *wpl;
    cudaGetSymbolAddress((void**)&xhi, gXhi);
    cudaGetSymbolAddress((void**)&xlo, gXlo);
    cudaGetSymbolAddress((void**)&wqh, gWqh);
    cudaGetSymbolAddress((void**)&wql, gWql);
    cudaGetSymbolAddress((void**)&wph, gWph);
    cudaGetSymbolAddress((void**)&wpl, gWpl);

    // split X into bf16 hi/lo
    split_kernel<<<(PP*NN*DD/4 + 255)/256, 256>>>(X, xhi, xlo, PP*NN*DD/4);
    // transpose+split weights
    tsplit_kernel<<<dim3(3*DD/32, DD/32), dim3(32,8)>>>(qkv_w, wqh, wql, DD, 3*DD);
    tsplit_kernel<<<dim3(DD/32, DD/32), dim3(32,8)>>>(proj_w, wph, wpl, DD, DD);
    // QKV projection (HMMA bf16x3)
    gemm_mma<<<dim3(3*DD/128, PP*NN/128), 256, GEMM_SMEM>>>(0, qkv_b, nullptr);
    // post-softmax mask term
    maskv_kernel<<<PP*HH, 256>>>(mask);
    // attention
    attn_kernel<<<dim3(NN/32, HH, PP), 128>>>();
    // output projection (HMMA bf16x3)
    gemm_mma<<<dim3(DD/128, PP*NN/128), 256, GEMM_SMEM>>>(1, proj_b, out);
}

// round 5
// speedup vs baseline: 2.3696x; 1.7083x over previous
#include <cuda_runtime.h>
#include <cuda_bf16.h>
#include <cstdint>

#define PP 8
#define NN 1024
#define DD 768
#define HH 12
#define HSZ 64
#define SCLOG2 11.5423594967f   // 8 * log2(e)

// ---- scratch (static) ----
__device__ float gMV[PP*HH*HSZ];
__device__ __nv_bfloat16 gXhi[PP*NN*DD];
__device__ __nv_bfloat16 gXlo[PP*NN*DD];
__device__ __nv_bfloat16 gWqh[3*DD*DD];
__device__ __nv_bfloat16 gWql[3*DD*DD];
__device__ __nv_bfloat16 gWph[DD*DD];
__device__ __nv_bfloat16 gWpl[DD*DD];
__device__ __nv_bfloat16 gCh[PP*NN*DD];
__device__ __nv_bfloat16 gCl[PP*NN*DD];
// attention operands, bf16 hi/lo. Q,K: [ph][n][hs]; V transposed: [ph][hs][n]
__device__ __nv_bfloat16 gQh[PP*HH*NN*HSZ];
__device__ __nv_bfloat16 gQl[PP*HH*NN*HSZ];
__device__ __nv_bfloat16 gKh[PP*HH*NN*HSZ];
__device__ __nv_bfloat16 gKl[PP*HH*NN*HSZ];
__device__ __nv_bfloat16 gVth[PP*HH*NN*HSZ];
__device__ __nv_bfloat16 gVtl[PP*HH*NN*HSZ];

// ================= helpers =================
__device__ __forceinline__ uint32_t smem_u32(const void* p) {
    uint32_t a;
    asm("{ .reg .u64 t; cvta.to.shared.u64 t, %1; cvt.u32.u64 %0, t; }" : "=r"(a) : "l"(p));
    return a;
}
__device__ __forceinline__ uint32_t lds32(uint32_t a) {
    uint32_t v;
    asm volatile("ld.shared.b32 %0, [%1];" : "=r"(v) : "r"(a));
    return v;
}
#define CP16(saddr, gptr) \
    asm volatile("cp.async.cg.shared.global [%0], [%1], 16;" :: "r"(saddr), "l"(gptr))
#define CP_COMMIT() asm volatile("cp.async.commit_group;" ::: "memory")
#define CP_WAIT1()  asm volatile("cp.async.wait_group 1;" ::: "memory")
#define CP_WAIT0()  asm volatile("cp.async.wait_group 0;" ::: "memory")

__device__ __forceinline__ void mma16816(float* c, const uint32_t* a, const uint32_t* b) {
    asm volatile("mma.sync.aligned.m16n8k16.row.col.f32.bf16.bf16.f32 "
                 "{%0,%1,%2,%3}, {%4,%5,%6,%7}, {%8,%9}, {%0,%1,%2,%3};"
                 : "+f"(c[0]), "+f"(c[1]), "+f"(c[2]), "+f"(c[3])
                 : "r"(a[0]), "r"(a[1]), "r"(a[2]), "r"(a[3]), "r"(b[0]), "r"(b[1]));
}
// pack two floats -> bf16x2 (v0 in low half)
__device__ __forceinline__ uint32_t pack2(float v0, float v1) {
    uint32_t r;
    asm("cvt.rn.bf16x2.f32 %0, %1, %2;" : "=r"(r) : "f"(v1), "f"(v0));
    return r;
}
// hi/lo split of a float pair into two bf16x2 words
__device__ __forceinline__ void split2(float v0, float v1, uint32_t& phi, uint32_t& plo) {
    phi = pack2(v0, v1);
    float h0 = __uint_as_float(phi << 16);
    float h1 = __uint_as_float(phi & 0xffff0000u);
    plo = pack2(v0 - h0, v1 - h1);
}

// ================= split / transpose-split =================
__global__ void split_kernel(const float* __restrict__ src,
                             __nv_bfloat16* __restrict__ hi,
                             __nv_bfloat16* __restrict__ lo, int n4) {
    int i = blockIdx.x * blockDim.x + threadIdx.x;
    if (i >= n4) return;
    float4 v = ((const float4*)src)[i];
    uint32_t h[2], l[2];
    split2(v.x, v.y, h[0], l[0]);
    split2(v.z, v.w, h[1], l[1]);
    ((uint2*)hi)[i] = make_uint2(h[0], h[1]);
    ((uint2*)lo)[i] = make_uint2(l[0], l[1]);
}

__global__ void tsplit_kernel(const float* __restrict__ W,
                              __nv_bfloat16* __restrict__ Th,
                              __nv_bfloat16* __restrict__ Tl, int K, int N) {
    __shared__ float t[32][33];
    int k0 = blockIdx.y * 32, n0 = blockIdx.x * 32;
    int tx = threadIdx.x, ty = threadIdx.y;
    #pragma unroll
    for (int i = 0; i < 4; i++)
        t[ty + 8*i][tx] = W[(size_t)(k0 + ty + 8*i) * N + n0 + tx];
    __syncthreads();
    #pragma unroll
    for (int i = 0; i < 4; i++) {
        float x = t[tx][ty + 8*i];
        __nv_bfloat16 h = __float2bfloat16_rn(x);
        __nv_bfloat16 l = __float2bfloat16_rn(x - __bfloat162float(h));
        size_t o = (size_t)(n0 + ty + 8*i) * K + k0 + tx;
        Th[o] = h; Tl[o] = l;
    }
}

// ================= bf16x3 GEMM via mma.sync =================
#define PADK 40
#define TILE_E (128*PADK)
#define BUF_BYTES (4*TILE_E*2)
#define GEMM_SMEM (2*BUF_BYTES)

__global__ __launch_bounds__(256, 1) void gemm_mma(int mode,
                                                   const float* __restrict__ bias,
                                                   float* __restrict__ out) {
    extern __shared__ __align__(16) char smem[];
    uint32_t sb = smem_u32(smem);
    int tid = threadIdx.x, wid = tid >> 5, lane = tid & 31;
    int wm = wid & 3, wn = wid >> 2;
    int row0 = blockIdx.y * 128, col0 = blockIdx.x * 128;
    int gid = lane >> 2, tig = lane & 3;

    const __nv_bfloat16* Ah = mode ? gCh : gXhi;
    const __nv_bfloat16* Al = mode ? gCl : gXlo;
    const __nv_bfloat16* Bh = mode ? gWph : gWqh;
    const __nv_bfloat16* Bl = mode ? gWpl : gWql;
    const __nv_bfloat16* srcs[4] = {Ah, Al, Bh, Bl};

    float acc[2][8][4];
    #pragma unroll
    for (int i = 0; i < 2; i++)
        #pragma unroll
        for (int j = 0; j < 8; j++)
            #pragma unroll
            for (int q = 0; q < 4; q++) acc[i][j][q] = 0.f;

    auto fill = [&](int s, int c) {
        int k0 = c * 32;
        uint32_t sbase = sb + s * BUF_BYTES;
        #pragma unroll
        for (int t = 0; t < 4; t++) {
            const __nv_bfloat16* src = srcs[t];
            int rbase = (t < 2) ? row0 : col0;
            #pragma unroll
            for (int j = 0; j < 2; j++) {
                int e = j * 256 + tid;
                int r = e >> 2, v = e & 3;
                uint32_t daddr = sbase + (uint32_t)(t * TILE_E + r * PADK + v * 8) * 2;
                const __nv_bfloat16* g = src + (size_t)(rbase + r) * DD + k0 + v * 8;
                CP16(daddr, g);
            }
        }
        CP_COMMIT();
    };

    fill(0, 0);
    for (int c = 0; c < 24; c++) {
        if (c < 23) fill((c + 1) & 1, c + 1);
        if (c < 23) CP_WAIT1(); else CP_WAIT0();
        __syncthreads();

        uint32_t base = sb + (c & 1) * BUF_BYTES;
        uint32_t Ahb = base, Alb = base + TILE_E*2;
        uint32_t Bhb = base + 2*TILE_E*2, Blb = base + 3*TILE_E*2;

        #pragma unroll
        for (int ks = 0; ks < 2; ks++) {
            int kcol = ks * 16 + tig * 2;
            uint32_t ah[2][4], al[2][4];
            #pragma unroll
            for (int mt = 0; mt < 2; mt++) {
                int r = wm * 32 + mt * 16 + gid;
                uint32_t o = (uint32_t)(r * PADK + kcol) * 2;
                ah[mt][0] = lds32(Ahb + o);
                ah[mt][1] = lds32(Ahb + o + 8*PADK*2);
                ah[mt][2] = lds32(Ahb + o + 16);
                ah[mt][3] = lds32(Ahb + o + 8*PADK*2 + 16);
                al[mt][0] = lds32(Alb + o);
                al[mt][1] = lds32(Alb + o + 8*PADK*2);
                al[mt][2] = lds32(Alb + o + 16);
                al[mt][3] = lds32(Alb + o + 8*PADK*2 + 16);
            }
            #pragma unroll
            for (int half = 0; half < 2; half++) {
                uint32_t bh[4][2], bl[4][2];
                #pragma unroll
                for (int nt = 0; nt < 4; nt++) {
                    int n = wn * 64 + half * 32 + nt * 8 + gid;
                    uint32_t o = (uint32_t)(n * PADK + kcol) * 2;
                    bh[nt][0] = lds32(Bhb + o);
                    bh[nt][1] = lds32(Bhb + o + 16);
                    bl[nt][0] = lds32(Blb + o);
                    bl[nt][1] = lds32(Blb + o + 16);
                }
                #pragma unroll
                for (int mt = 0; mt < 2; mt++)
                    #pragma unroll
                    for (int nt = 0; nt < 4; nt++) {
                        float* cc = acc[mt][half * 4 + nt];
                        mma16816(cc, ah[mt], bh[nt]);
                        mma16816(cc, ah[mt], bl[nt]);
                        mma16816(cc, al[mt], bh[nt]);
                    }
            }
        }
        __syncthreads();
    }

    // ---- epilogue ----
    #pragma unroll
    for (int mt = 0; mt < 2; mt++) {
        int m_lo = row0 + wm * 32 + mt * 16 + gid;
        int m_hi = m_lo + 8;
        #pragma unroll
        for (int j = 0; j < 8; j++) {
            int nc = col0 + wn * 64 + (j >> 2) * 32 + (j & 3) * 8 + tig * 2;
            float b0 = bias[nc], b1 = bias[nc + 1];
            float* cc = acc[mt][j];
            float v0 = cc[0] + b0, v1 = cc[1] + b1;  // row m_lo
            float v2 = cc[2] + b0, v3 = cc[3] + b1;  // row m_hi
            if (mode == 0) {
                int which = (nc >= 2*DD) ? 2 : ((nc >= DD) ? 1 : 0);
                int rem = nc - which * DD;
                int h = rem >> 6, hs = rem & 63;
                int p0 = m_lo >> 10, n0 = m_lo & 1023;
                int p1 = m_hi >> 10, n1 = m_hi & 1023;
                int ph0 = p0 * HH + h, ph1 = p1 * HH + h;
                uint32_t whi, wlo;
                if (which == 2) {
                    size_t r0 = ((size_t)ph0 * HSZ + hs) * NN;
                    size_t r1 = ((size_t)ph1 * HSZ + hs) * NN;
                    split2(v0, v1, whi, wlo);
                    gVth[r0 + n0] = __ushort_as_bfloat16((unsigned short)(whi & 0xffff));
                    gVth[r0 + NN + n0] = __ushort_as_bfloat16((unsigned short)(whi >> 16));
                    gVtl[r0 + n0] = __ushort_as_bfloat16((unsigned short)(wlo & 0xffff));
                    gVtl[r0 + NN + n0] = __ushort_as_bfloat16((unsigned short)(wlo >> 16));
                    split2(v2, v3, whi, wlo);
                    gVth[r1 + n1] = __ushort_as_bfloat16((unsigned short)(whi & 0xffff));
                    gVth[r1 + NN + n1] = __ushort_as_bfloat16((unsigned short)(whi >> 16));
                    gVtl[r1 + n1] = __ushort_as_bfloat16((unsigned short)(wlo & 0xffff));
                    gVtl[r1 + NN + n1] = __ushort_as_bfloat16((unsigned short)(wlo >> 16));
                } else {
                    __nv_bfloat16* dh = which ? gKh : gQh;
                    __nv_bfloat16* dl = which ? gKl : gQl;
                    size_t o0 = (((size_t)ph0 << 10) + n0) * HSZ + hs;
                    size_t o1 = (((size_t)ph1 << 10) + n1) * HSZ + hs;
                    split2(v0, v1, whi, wlo);
                    *(uint32_t*)&dh[o0] = whi; *(uint32_t*)&dl[o0] = wlo;
                    split2(v2, v3, whi, wlo);
                    *(uint32_t*)&dh[o1] = whi; *(uint32_t*)&dl[o1] = wlo;
                }
            } else {
                *(float2*)&out[(size_t)m_lo * DD + nc] = make_float2(v0, v1);
                *(float2*)&out[(size_t)m_hi * DD + nc] = make_float2(v2, v3);
            }
        }
    }
}

// ================= post-softmax mask term =================
__global__ void maskv_kernel(const float* __restrict__ mask) {
    int ph = blockIdx.x;
    int p = ph / HH;
    int w = threadIdx.x >> 5, lane = threadIdx.x & 31;
    const float* mp = mask + (size_t)p * NN;
    #pragma unroll
    for (int i = 0; i < 8; i++) {
        int hs = w * 8 + i;
        const __nv_bfloat16* vh = gVth + ((size_t)ph * HSZ + hs) * NN;
        const __nv_bfloat16* vl = gVtl + ((size_t)ph * HSZ + hs) * NN;
        float acc = 0.f;
        for (int k = lane; k < NN; k += 32)
            acc += mp[k] * (__bfloat162float(vh[k]) + __bfloat162float(vl[k]));
        #pragma unroll
        for (int s = 16; s > 0; s >>= 1) acc += __shfl_xor_sync(0xffffffffu, acc, s);
        if (lane == 0) gMV[ph * HSZ + hs] = acc;
    }
}

// ================= flash attention via mma.sync (bf16x3) =================
// CTA = (p, h, 128 q-rows), 8 warps x 16 q-rows. K-block 64, double buffered.
// smem per buffer: Kh[64][72], Kl, Vth[64][72], Vtl (Vt rows = hs, cols = key)
#define AKS 72
#define KTILE_B (64*AKS*2)          // 9216 B
#define ABUF_B (4*KTILE_B)          // 36864 B
#define ATTN_SMEM (2*ABUF_B)        // 73728 B

__global__ __launch_bounds__(256, 1) void attn_mma() {
    extern __shared__ __align__(16) char smem[];
    uint32_t sb = smem_u32(smem);
    int tid = threadIdx.x, wid = tid >> 5, lane = tid & 31;
    int gid = lane >> 2, tig = lane & 3;
    int qb = blockIdx.x, h = blockIdx.y, p = blockIdx.z;
    int ph = p * HH + h;

    // ---- preload Q fragments (hi/lo), warp rows qb*128 + wid*16 + {gid, gid+8}
    uint32_t qh[4][4], ql[4][4];
    {
        const __nv_bfloat16* base_h = gQh + ((size_t)ph * NN + qb*128 + wid*16) * HSZ;
        const __nv_bfloat16* base_l = gQl + ((size_t)ph * NN + qb*128 + wid*16) * HSZ;
        #pragma unroll
        for (int kk = 0; kk < 4; kk++) {
            int c = kk * 16 + tig * 2;
            qh[kk][0] = *(const uint32_t*)(base_h + (size_t)gid * HSZ + c);
            qh[kk][1] = *(const uint32_t*)(base_h + (size_t)(gid+8) * HSZ + c);
            qh[kk][2] = *(const uint32_t*)(base_h + (size_t)gid * HSZ + c + 8);
            qh[kk][3] = *(const uint32_t*)(base_h + (size_t)(gid+8) * HSZ + c + 8);
            ql[kk][0] = *(const uint32_t*)(base_l + (size_t)gid * HSZ + c);
            ql[kk][1] = *(const uint32_t*)(base_l + (size_t)(gid+8) * HSZ + c);
            ql[kk][2] = *(const uint32_t*)(base_l + (size_t)gid * HSZ + c + 8);
            ql[kk][3] = *(const uint32_t*)(base_l + (size_t)(gid+8) * HSZ + c + 8);
        }
    }

    float oacc[8][4];
    #pragma unroll
    for (int i = 0; i < 8; i++)
        #pragma unroll
        for (int j = 0; j < 4; j++) oacc[i][j] = 0.f;
    float m0 = -1e30f, m1 = -1e30f, l0 = 0.f, l1 = 0.f;

    const __nv_bfloat16* Kh_g = gKh + (size_t)ph * NN * HSZ;
    const __nv_bfloat16* Kl_g = gKl + (size_t)ph * NN * HSZ;
    const __nv_bfloat16* Vh_g = gVth + (size_t)ph * HSZ * NN;
    const __nv_bfloat16* Vl_g = gVtl + (size_t)ph * HSZ * NN;

    auto fill = [&](int s, int kb) {
        uint32_t base = sb + s * ABUF_B;
        // K tile: 64 keys x 64 hs  (8 x 16B chunks per row)
        #pragma unroll
        for (int j = 0; j < 2; j++) {
            int e = j * 256 + tid;           // 0..511
            int r = e >> 3, ch = e & 7;
            uint32_t d = base + (uint32_t)(r * AKS + ch * 8) * 2;
            const __nv_bfloat16* gh = Kh_g + (size_t)(kb*64 + r) * HSZ + ch * 8;
            const __nv_bfloat16* gl = Kl_g + (size_t)(kb*64 + r) * HSZ + ch * 8;
            CP16(d, gh);
            CP16(d + KTILE_B, gl);
        }
        // Vt tile: 64 hs x 64 keys  (8 x 16B chunks per row) -- FIXED
        #pragma unroll
        for (int j = 0; j < 2; j++) {
            int e = j * 256 + tid;           // 0..511
            int r = e >> 3, ch = e & 7;
            uint32_t d = base + 2*KTILE_B + (uint32_t)(r * AKS + ch * 8) * 2;
            const __nv_bfloat16* gh = Vh_g + (size_t)r * NN + kb*64 + ch * 8;
            const __nv_bfloat16* gl = Vl_g + (size_t)r * NN + kb*64 + ch * 8;
            CP16(d, gh);
            CP16(d + KTILE_B, gl);
        }
        CP_COMMIT();
    };

    fill(0, 0);
    for (int kb = 0; kb < 16; kb++) {
        if (kb < 15) fill((kb + 1) & 1, kb + 1);
        if (kb < 15) CP_WAIT1(); else CP_WAIT0();
        __syncthreads();

        uint32_t base = sb + (kb & 1) * ABUF_B;
        uint32_t Khb = base, Klb = base + KTILE_B;
        uint32_t Vhb = base + 2*KTILE_B, Vlb = base + 3*KTILE_B;

        // ---- S = Q K^T (16 x 64 per warp), 3-term hi/lo
        float sacc[8][4];
        #pragma unroll
        for (int nt = 0; nt < 8; nt++) {
            #pragma unroll
            for (int j = 0; j < 4; j++) sacc[nt][j] = 0.f;
            uint32_t ro = (uint32_t)((nt*8 + gid) * AKS) * 2;
            #pragma unroll
            for (int kk = 0; kk < 4; kk++) {
                uint32_t co = (uint32_t)(kk*16 + tig*2) * 2;
                uint32_t bh[2], bl[2];
                bh[0] = lds32(Khb + ro + co);
                bh[1] = lds32(Khb + ro + co + 16);
                bl[0] = lds32(Klb + ro + co);
                bl[1] = lds32(Klb + ro + co + 16);
                mma16816(sacc[nt], qh[kk], bh);
                mma16816(sacc[nt], qh[kk], bl);
                mma16816(sacc[nt], ql[kk], bh);
            }
        }

        // ---- online softmax (scale x8 folded into exp2 constant)
        float mx0 = -1e30f, mx1 = -1e30f;
        #pragma unroll
        for (int nt = 0; nt < 8; nt++) {
            mx0 = fmaxf(mx0, fmaxf(sacc[nt][0], sacc[nt][1]));
            mx1 = fmaxf(mx1, fmaxf(sacc[nt][2], sacc[nt][3]));
        }
        mx0 = fmaxf(mx0, __shfl_xor_sync(0xffffffffu, mx0, 1));
        mx0 = fmaxf(mx0, __shfl_xor_sync(0xffffffffu, mx0, 2));
        mx1 = fmaxf(mx1, __shfl_xor_sync(0xffffffffu, mx1, 1));
        mx1 = fmaxf(mx1, __shfl_xor_sync(0xffffffffu, mx1, 2));
        float nm0 = fmaxf(m0, mx0), nm1 = fmaxf(m1, mx1);
        float corr0 = exp2f((m0 - nm0) * SCLOG2);
        float corr1 = exp2f((m1 - nm1) * SCLOG2);
        m0 = nm0; m1 = nm1;
        float rs0 = 0.f, rs1 = 0.f;
        #pragma unroll
        for (int nt = 0; nt < 8; nt++) {
            sacc[nt][0] = exp2f((sacc[nt][0] - nm0) * SCLOG2);
            sacc[nt][1] = exp2f((sacc[nt][1] - nm0) * SCLOG2);
            sacc[nt][2] = exp2f((sacc[nt][2] - nm1) * SCLOG2);
            sacc[nt][3] = exp2f((sacc[nt][3] - nm1) * SCLOG2);
            rs0 += sacc[nt][0] + sacc[nt][1];
            rs1 += sacc[nt][2] + sacc[nt][3];
        }
        rs0 += __shfl_xor_sync(0xffffffffu, rs0, 1);
        rs0 += __shfl_xor_sync(0xffffffffu, rs0, 2);
        rs1 += __shfl_xor_sync(0xffffffffu, rs1, 1);
        rs1 += __shfl_xor_sync(0xffffffffu, rs1, 2);
        l0 = l0 * corr0 + rs0;
        l1 = l1 * corr1 + rs1;
        #pragma unroll
        for (int nt = 0; nt < 8; nt++) {
            oacc[nt][0] *= corr0; oacc[nt][1] *= corr0;
            oacc[nt][2] *= corr1; oacc[nt][3] *= corr1;
        }

        // ---- O += P V, P in registers (hi/lo), V from smem
        #pragma unroll
        for (int kblk = 0; kblk < 4; kblk++) {
            uint32_t ah[4], al[4];
            split2(sacc[2*kblk][0],   sacc[2*kblk][1],   ah[0], al[0]);
            split2(sacc[2*kblk][2],   sacc[2*kblk][3],   ah[1], al[1]);
            split2(sacc[2*kblk+1][0], sacc[2*kblk+1][1], ah[2], al[2]);
            split2(sacc[2*kblk+1][2], sacc[2*kblk+1][3], ah[3], al[3]);
            uint32_t co = (uint32_t)(kblk*16 + tig*2) * 2;
            #pragma unroll
            for (int nt = 0; nt < 8; nt++) {
                uint32_t ro = (uint32_t)((nt*8 + gid) * AKS) * 2;
                uint32_t bh[2], bl[2];
                bh[0] = lds32(Vhb + ro + co);
                bh[1] = lds32(Vhb + ro + co + 16);
                bl[0] = lds32(Vlb + ro + co);
                bl[1] = lds32(Vlb + ro + co + 16);
                mma16816(oacc[nt], ah, bh);
                mma16816(oacc[nt], ah, bl);
                mma16816(oacc[nt], al, bh);
            }
        }
        __syncthreads();
    }

    // ---- epilogue: ctx = O/l + maskV, stored bf16 hi/lo
    float inv0 = 1.0f / l0, inv1 = 1.0f / l1;
    int q_lo = qb*128 + wid*16 + gid;
    int q_hi = q_lo + 8;
    #pragma unroll
    for (int nt = 0; nt < 8; nt++) {
        int hs = nt*8 + tig*2;
        float mv0 = gMV[ph*HSZ + hs], mv1 = gMV[ph*HSZ + hs + 1];
        float v0 = oacc[nt][0]*inv0 + mv0, v1 = oacc[nt][1]*inv0 + mv1;
        float v2 = oacc[nt][2]*inv1 + mv0, v3 = oacc[nt][3]*inv1 + mv1;
        size_t o0 = ((size_t)p*NN + q_lo) * DD + h*HSZ + hs;
        size_t o1 = ((size_t)p*NN + q_hi) * DD + h*HSZ + hs;
        uint32_t whi, wlo;
        split2(v0, v1, whi, wlo);
        *(uint32_t*)&gCh[o0] = whi; *(uint32_t*)&gCl[o0] = wlo;
        split2(v2, v3, whi, wlo);
        *(uint32_t*)&gCh[o1] = whi; *(uint32_t*)&gCl[o1] = wlo;
    }
}

extern "C" void kernel_launch(void* const* d_in, const int* in_sizes, int n_in,
                              void* d_out, int out_size) {
    const float* X      = (const float*)d_in[0];
    const float* mask   = (const float*)d_in[1];
    const float* qkv_w  = (const float*)d_in[2];
    const float* qkv_b  = (const float*)d_in[3];
    const float* proj_w = (const float*)d_in[4];
    const float* proj_b = (const float*)d_in[5];
    float* out = (float*)d_out;

    cudaFuncSetAttribute(gemm_mma, cudaFuncAttributeMaxDynamicSharedMemorySize, GEMM_SMEM);
    cudaFuncSetAttribute(attn_mma, cudaFuncAttributeMaxDynamicSharedMemorySize, ATTN_SMEM);

    __nv_bfloat16 *xhi, *xlo, *wqh, *wql, *wph, *wpl;
    cudaGetSymbolAddress((void**)&xhi, gXhi);
    cudaGetSymbolAddress((void**)&xlo, gXlo);
    cudaGetSymbolAddress((void**)&wqh, gWqh);
    cudaGetSymbolAddress((void**)&wql, gWql);
    cudaGetSymbolAddress((void**)&wph, gWph);
    cudaGetSymbolAddress((void**)&wpl, gWpl);

    split_kernel<<<(PP*NN*DD/4 + 255)/256, 256>>>(X, xhi, xlo, PP*NN*DD/4);
    tsplit_kernel<<<dim3(3*DD/32, DD/32), dim3(32,8)>>>(qkv_w, wqh, wql, DD, 3*DD);
    tsplit_kernel<<<dim3(DD/32, DD/32), dim3(32,8)>>>(proj_w, wph, wpl, DD, DD);
    gemm_mma<<<dim3(3*DD/128, PP*NN/128), 256, GEMM_SMEM>>>(0, qkv_b, nullptr);
    maskv_kernel<<<PP*HH, 256>>>(mask);
    attn_mma<<<dim3(NN/128, HH, PP), 256, ATTN_SMEM>>>();
    gemm_mma<<<dim3(DD/128, PP*NN/128), 256, GEMM_SMEM>>>(1, proj_b, out);
}

// round 6
// speedup vs baseline: 2.4528x; 1.0351x over previous
#include <cuda_runtime.h>
#include <cuda_bf16.h>
#include <cstdint>

#define PP 8
#define NN 1024
#define DD 768
#define HH 12
#define HSZ 64
#define SCLOG2 11.5423594967f   // 8 * log2(e)

// ---- scratch (static) ----
__device__ float gMV[PP*HH*HSZ];
__device__ __nv_bfloat16 gXhi[PP*NN*DD];
__device__ __nv_bfloat16 gXlo[PP*NN*DD];
__device__ __nv_bfloat16 gWqh[3*DD*DD];
__device__ __nv_bfloat16 gWql[3*DD*DD];
__device__ __nv_bfloat16 gWph[DD*DD];
__device__ __nv_bfloat16 gWpl[DD*DD];
__device__ __nv_bfloat16 gCh[PP*NN*DD];
__device__ __nv_bfloat16 gCl[PP*NN*DD];
// attention operands, bf16 hi/lo. Q,K: [ph][n][hs]; V transposed: [ph][hs][n]
__device__ __nv_bfloat16 gQh[PP*HH*NN*HSZ];
__device__ __nv_bfloat16 gQl[PP*HH*NN*HSZ];
__device__ __nv_bfloat16 gKh[PP*HH*NN*HSZ];
__device__ __nv_bfloat16 gKl[PP*HH*NN*HSZ];
__device__ __nv_bfloat16 gVth[PP*HH*NN*HSZ];
__device__ __nv_bfloat16 gVtl[PP*HH*NN*HSZ];

// ================= helpers =================
__device__ __forceinline__ uint32_t smem_u32(const void* p) {
    uint32_t a;
    asm("{ .reg .u64 t; cvta.to.shared.u64 t, %1; cvt.u32.u64 %0, t; }" : "=r"(a) : "l"(p));
    return a;
}
__device__ __forceinline__ uint32_t lds32(uint32_t a) {
    uint32_t v;
    asm volatile("ld.shared.b32 %0, [%1];" : "=r"(v) : "r"(a));
    return v;
}
#define CP16(saddr, gptr) \
    asm volatile("cp.async.cg.shared.global [%0], [%1], 16;" :: "r"(saddr), "l"(gptr))
#define CP_COMMIT() asm volatile("cp.async.commit_group;" ::: "memory")
#define CP_WAIT1()  asm volatile("cp.async.wait_group 1;" ::: "memory")
#define CP_WAIT0()  asm volatile("cp.async.wait_group 0;" ::: "memory")

__device__ __forceinline__ void mma16816(float* c, const uint32_t* a, const uint32_t* b) {
    asm volatile("mma.sync.aligned.m16n8k16.row.col.f32.bf16.bf16.f32 "
                 "{%0,%1,%2,%3}, {%4,%5,%6,%7}, {%8,%9}, {%0,%1,%2,%3};"
                 : "+f"(c[0]), "+f"(c[1]), "+f"(c[2]), "+f"(c[3])
                 : "r"(a[0]), "r"(a[1]), "r"(a[2]), "r"(a[3]), "r"(b[0]), "r"(b[1]));
}
// pack two floats -> bf16x2 (v0 in low half)
__device__ __forceinline__ uint32_t pack2(float v0, float v1) {
    uint32_t r;
    asm("cvt.rn.bf16x2.f32 %0, %1, %2;" : "=r"(r) : "f"(v1), "f"(v0));
    return r;
}
// hi/lo split of a float pair into two bf16x2 words
__device__ __forceinline__ void split2(float v0, float v1, uint32_t& phi, uint32_t& plo) {
    phi = pack2(v0, v1);
    float h0 = __uint_as_float(phi << 16);
    float h1 = __uint_as_float(phi & 0xffff0000u);
    plo = pack2(v0 - h0, v1 - h1);
}

// ================= split / transpose-split =================
__global__ void split_kernel(const float* __restrict__ src,
                             __nv_bfloat16* __restrict__ hi,
                             __nv_bfloat16* __restrict__ lo, int n4) {
    int i = blockIdx.x * blockDim.x + threadIdx.x;
    if (i >= n4) return;
    float4 v = ((const float4*)src)[i];
    uint32_t h[2], l[2];
    split2(v.x, v.y, h[0], l[0]);
    split2(v.z, v.w, h[1], l[1]);
    ((uint2*)hi)[i] = make_uint2(h[0], h[1]);
    ((uint2*)lo)[i] = make_uint2(l[0], l[1]);
}

__global__ void tsplit_kernel(const float* __restrict__ W,
                              __nv_bfloat16* __restrict__ Th,
                              __nv_bfloat16* __restrict__ Tl, int K, int N) {
    __shared__ float t[32][33];
    int k0 = blockIdx.y * 32, n0 = blockIdx.x * 32;
    int tx = threadIdx.x, ty = threadIdx.y;
    #pragma unroll
    for (int i = 0; i < 4; i++)
        t[ty + 8*i][tx] = W[(size_t)(k0 + ty + 8*i) * N + n0 + tx];
    __syncthreads();
    #pragma unroll
    for (int i = 0; i < 4; i++) {
        float x = t[tx][ty + 8*i];
        __nv_bfloat16 h = __float2bfloat16_rn(x);
        __nv_bfloat16 l = __float2bfloat16_rn(x - __bfloat162float(h));
        size_t o = (size_t)(n0 + ty + 8*i) * K + k0 + tx;
        Th[o] = h; Tl[o] = l;
    }
}

// ================= bf16x3 GEMM via mma.sync =================
// CTA tile 128(m) x 256(n), 512 threads (16 warps = 4m x 4n, warp tile 32x64),
// K-chunk 32, double-buffered cp.async.
#define PADK 40
#define TILE_AE (128*PADK)
#define TILE_BE (256*PADK)
#define ABUF ((2*TILE_AE + 2*TILE_BE)*2)   // 61440 B per buffer
#define GEMM_SMEM (2*ABUF)                 // 122880 B

__global__ __launch_bounds__(512, 1) void gemm_mma(int mode,
                                                   const float* __restrict__ bias,
                                                   float* __restrict__ out) {
    extern __shared__ __align__(16) char smem[];
    uint32_t sb = smem_u32(smem);
    int tid = threadIdx.x, wid = tid >> 5, lane = tid & 31;
    int wm = wid & 3, wn = wid >> 2;
    int row0 = blockIdx.y * 128, col0 = blockIdx.x * 256;
    int gid = lane >> 2, tig = lane & 3;

    const __nv_bfloat16* Ah = mode ? gCh : gXhi;
    const __nv_bfloat16* Al = mode ? gCl : gXlo;
    const __nv_bfloat16* Bh = mode ? gWph : gWqh;
    const __nv_bfloat16* Bl = mode ? gWpl : gWql;

    float acc[2][8][4];
    #pragma unroll
    for (int i = 0; i < 2; i++)
        #pragma unroll
        for (int j = 0; j < 8; j++)
            #pragma unroll
            for (int q = 0; q < 4; q++) acc[i][j][q] = 0.f;

    auto fill = [&](int s, int c) {
        int k0 = c * 32;
        uint32_t sbase = sb + s * ABUF;
        // A: 128 rows x 4 chunks = 512 cp16 (hi) + 512 (lo)
        {
            int r = tid >> 2, v = tid & 3;
            uint32_t d = sbase + (uint32_t)(r * PADK + v * 8) * 2;
            size_t go = (size_t)(row0 + r) * DD + k0 + v * 8;
            CP16(d, Ah + go);
            CP16(d + TILE_AE*2, Al + go);
        }
        // B: 256 rows x 4 chunks = 1024 cp16 (hi) + 1024 (lo)
        #pragma unroll
        for (int j = 0; j < 2; j++) {
            int e = j * 512 + tid;
            int r = e >> 2, v = e & 3;
            uint32_t d = sbase + 2*TILE_AE*2 + (uint32_t)(r * PADK + v * 8) * 2;
            size_t go = (size_t)(col0 + r) * DD + k0 + v * 8;
            CP16(d, Bh + go);
            CP16(d + TILE_BE*2, Bl + go);
        }
        CP_COMMIT();
    };

    fill(0, 0);
    for (int c = 0; c < 24; c++) {
        if (c < 23) fill((c + 1) & 1, c + 1);
        if (c < 23) CP_WAIT1(); else CP_WAIT0();
        __syncthreads();

        uint32_t base = sb + (c & 1) * ABUF;
        uint32_t Ahb = base, Alb = base + TILE_AE*2;
        uint32_t Bhb = base + 2*TILE_AE*2, Blb = Bhb + TILE_BE*2;

        #pragma unroll
        for (int ks = 0; ks < 2; ks++) {
            int kcol = ks * 16 + tig * 2;
            uint32_t ah[2][4], al[2][4];
            #pragma unroll
            for (int mt = 0; mt < 2; mt++) {
                int r = wm * 32 + mt * 16 + gid;
                uint32_t o = (uint32_t)(r * PADK + kcol) * 2;
                ah[mt][0] = lds32(Ahb + o);
                ah[mt][1] = lds32(Ahb + o + 8*PADK*2);
                ah[mt][2] = lds32(Ahb + o + 16);
                ah[mt][3] = lds32(Ahb + o + 8*PADK*2 + 16);
                al[mt][0] = lds32(Alb + o);
                al[mt][1] = lds32(Alb + o + 8*PADK*2);
                al[mt][2] = lds32(Alb + o + 16);
                al[mt][3] = lds32(Alb + o + 8*PADK*2 + 16);
            }
            #pragma unroll
            for (int half = 0; half < 2; half++) {
                uint32_t bh[4][2], bl[4][2];
                #pragma unroll
                for (int nt = 0; nt < 4; nt++) {
                    int n = wn * 64 + half * 32 + nt * 8 + gid;
                    uint32_t o = (uint32_t)(n * PADK + kcol) * 2;
                    bh[nt][0] = lds32(Bhb + o);
                    bh[nt][1] = lds32(Bhb + o + 16);
                    bl[nt][0] = lds32(Blb + o);
                    bl[nt][1] = lds32(Blb + o + 16);
                }
                #pragma unroll
                for (int mt = 0; mt < 2; mt++)
                    #pragma unroll
                    for (int nt = 0; nt < 4; nt++) {
                        float* cc = acc[mt][half * 4 + nt];
                        mma16816(cc, ah[mt], bh[nt]);
                        mma16816(cc, ah[mt], bl[nt]);
                        mma16816(cc, al[mt], bh[nt]);
                    }
            }
        }
        __syncthreads();
    }

    // ---- epilogue ----
    #pragma unroll
    for (int mt = 0; mt < 2; mt++) {
        int m_lo = row0 + wm * 32 + mt * 16 + gid;
        int m_hi = m_lo + 8;
        #pragma unroll
        for (int j = 0; j < 8; j++) {
            int nc = col0 + wn * 64 + (j >> 2) * 32 + (j & 3) * 8 + tig * 2;
            float b0 = bias[nc], b1 = bias[nc + 1];
            float* cc = acc[mt][j];
            float v0 = cc[0] + b0, v1 = cc[1] + b1;  // row m_lo
            float v2 = cc[2] + b0, v3 = cc[3] + b1;  // row m_hi
            if (mode == 0) {
                int which = (nc >= 2*DD) ? 2 : ((nc >= DD) ? 1 : 0);
                int rem = nc - which * DD;
                int h = rem >> 6, hs = rem & 63;
                int p0 = m_lo >> 10, n0 = m_lo & 1023;
                int p1 = m_hi >> 10, n1 = m_hi & 1023;
                int ph0 = p0 * HH + h, ph1 = p1 * HH + h;
                uint32_t whi, wlo;
                if (which == 2) {
                    size_t r0 = ((size_t)ph0 * HSZ + hs) * NN;
                    size_t r1 = ((size_t)ph1 * HSZ + hs) * NN;
                    split2(v0, v1, whi, wlo);
                    gVth[r0 + n0] = __ushort_as_bfloat16((unsigned short)(whi & 0xffff));
                    gVth[r0 + NN + n0] = __ushort_as_bfloat16((unsigned short)(whi >> 16));
                    gVtl[r0 + n0] = __ushort_as_bfloat16((unsigned short)(wlo & 0xffff));
                    gVtl[r0 + NN + n0] = __ushort_as_bfloat16((unsigned short)(wlo >> 16));
                    split2(v2, v3, whi, wlo);
                    gVth[r1 + n1] = __ushort_as_bfloat16((unsigned short)(whi & 0xffff));
                    gVth[r1 + NN + n1] = __ushort_as_bfloat16((unsigned short)(whi >> 16));
                    gVtl[r1 + n1] = __ushort_as_bfloat16((unsigned short)(wlo & 0xffff));
                    gVtl[r1 + NN + n1] = __ushort_as_bfloat16((unsigned short)(wlo >> 16));
                } else {
                    __nv_bfloat16* dh = which ? gKh : gQh;
                    __nv_bfloat16* dl = which ? gKl : gQl;
                    size_t o0 = (((size_t)ph0 << 10) + n0) * HSZ + hs;
                    size_t o1 = (((size_t)ph1 << 10) + n1) * HSZ + hs;
                    split2(v0, v1, whi, wlo);
                    *(uint32_t*)&dh[o0] = whi; *(uint32_t*)&dl[o0] = wlo;
                    split2(v2, v3, whi, wlo);
                    *(uint32_t*)&dh[o1] = whi; *(uint32_t*)&dl[o1] = wlo;
                }
            } else {
                *(float2*)&out[(size_t)m_lo * DD + nc] = make_float2(v0, v1);
                *(float2*)&out[(size_t)m_hi * DD + nc] = make_float2(v2, v3);
            }
        }
    }
}

// ================= post-softmax mask term =================
__global__ void maskv_kernel(const float* __restrict__ mask) {
    int ph = blockIdx.x;
    int p = ph / HH;
    int w = threadIdx.x >> 5, lane = threadIdx.x & 31;
    const float* mp = mask + (size_t)p * NN;
    #pragma unroll
    for (int i = 0; i < 8; i++) {
        int hs = w * 8 + i;
        const __nv_bfloat16* vh = gVth + ((size_t)ph * HSZ + hs) * NN;
        const __nv_bfloat16* vl = gVtl + ((size_t)ph * HSZ + hs) * NN;
        float acc = 0.f;
        for (int k = lane; k < NN; k += 32)
            acc += mp[k] * (__bfloat162float(vh[k]) + __bfloat162float(vl[k]));
        #pragma unroll
        for (int s = 16; s > 0; s >>= 1) acc += __shfl_xor_sync(0xffffffffu, acc, s);
        if (lane == 0) gMV[ph * HSZ + hs] = acc;
    }
}

// ================= flash attention via mma.sync (bf16x3) =================
// CTA = (p, h, 256 q-rows), 512 threads = 16 warps x 16 q-rows.
// K-block 64, double buffered. smem per buffer: Kh[64][72], Kl, Vth[64][72], Vtl
#define AKS 72
#define KTILE_B (64*AKS*2)          // 9216 B
#define ABUF_B (4*KTILE_B)          // 36864 B
#define ATTN_SMEM (2*ABUF_B)        // 73728 B

__global__ __launch_bounds__(512, 1) void attn_mma() {
    extern __shared__ __align__(16) char smem[];
    uint32_t sb = smem_u32(smem);
    int tid = threadIdx.x, wid = tid >> 5, lane = tid & 31;
    int gid = lane >> 2, tig = lane & 3;
    int qb = blockIdx.x, h = blockIdx.y, p = blockIdx.z;
    int ph = p * HH + h;
    int q0 = qb * 256 + wid * 16;    // warp's first q row

    // ---- preload Q fragments (hi/lo), warp rows q0 + {gid, gid+8}
    uint32_t qh[4][4], ql[4][4];
    {
        const __nv_bfloat16* base_h = gQh + ((size_t)ph * NN + q0) * HSZ;
        const __nv_bfloat16* base_l = gQl + ((size_t)ph * NN + q0) * HSZ;
        #pragma unroll
        for (int kk = 0; kk < 4; kk++) {
            int c = kk * 16 + tig * 2;
            qh[kk][0] = *(const uint32_t*)(base_h + (size_t)gid * HSZ + c);
            qh[kk][1] = *(const uint32_t*)(base_h + (size_t)(gid+8) * HSZ + c);
            qh[kk][2] = *(const uint32_t*)(base_h + (size_t)gid * HSZ + c + 8);
            qh[kk][3] = *(const uint32_t*)(base_h + (size_t)(gid+8) * HSZ + c + 8);
            ql[kk][0] = *(const uint32_t*)(base_l + (size_t)gid * HSZ + c);
            ql[kk][1] = *(const uint32_t*)(base_l + (size_t)(gid+8) * HSZ + c);
            ql[kk][2] = *(const uint32_t*)(base_l + (size_t)gid * HSZ + c + 8);
            ql[kk][3] = *(const uint32_t*)(base_l + (size_t)(gid+8) * HSZ + c + 8);
        }
    }

    float oacc[8][4];
    #pragma unroll
    for (int i = 0; i < 8; i++)
        #pragma unroll
        for (int j = 0; j < 4; j++) oacc[i][j] = 0.f;
    float m0 = -1e30f, m1 = -1e30f, l0 = 0.f, l1 = 0.f;

    const __nv_bfloat16* Kh_g = gKh + (size_t)ph * NN * HSZ;
    const __nv_bfloat16* Kl_g = gKl + (size_t)ph * NN * HSZ;
    const __nv_bfloat16* Vh_g = gVth + (size_t)ph * HSZ * NN;
    const __nv_bfloat16* Vl_g = gVtl + (size_t)ph * HSZ * NN;

    auto fill = [&](int s, int kb) {
        uint32_t base = sb + s * ABUF_B;
        // K tile: 64 keys x 64 hs (512 x 16B chunks), one per thread
        {
            int r = tid >> 3, ch = tid & 7;
            uint32_t d = base + (uint32_t)(r * AKS + ch * 8) * 2;
            const __nv_bfloat16* gh = Kh_g + (size_t)(kb*64 + r) * HSZ + ch * 8;
            const __nv_bfloat16* gl = Kl_g + (size_t)(kb*64 + r) * HSZ + ch * 8;
            CP16(d, gh);
            CP16(d + KTILE_B, gl);
        }
        // Vt tile: 64 hs x 64 keys (512 x 16B chunks), one per thread
        {
            int r = tid >> 3, ch = tid & 7;
            uint32_t d = base + 2*KTILE_B + (uint32_t)(r * AKS + ch * 8) * 2;
            const __nv_bfloat16* gh = Vh_g + (size_t)r * NN + kb*64 + ch * 8;
            const __nv_bfloat16* gl = Vl_g + (size_t)r * NN + kb*64 + ch * 8;
            CP16(d, gh);
            CP16(d + KTILE_B, gl);
        }
        CP_COMMIT();
    };

    fill(0, 0);
    for (int kb = 0; kb < 16; kb++) {
        if (kb < 15) fill((kb + 1) & 1, kb + 1);
        if (kb < 15) CP_WAIT1(); else CP_WAIT0();
        __syncthreads();

        uint32_t base = sb + (kb & 1) * ABUF_B;
        uint32_t Khb = base, Klb = base + KTILE_B;
        uint32_t Vhb = base + 2*KTILE_B, Vlb = base + 3*KTILE_B;

        // ---- S = Q K^T (16 x 64 per warp), 3-term hi/lo
        float sacc[8][4];
        #pragma unroll
        for (int nt = 0; nt < 8; nt++) {
            #pragma unroll
            for (int j = 0; j < 4; j++) sacc[nt][j] = 0.f;
            uint32_t ro = (uint32_t)((nt*8 + gid) * AKS) * 2;
            #pragma unroll
            for (int kk = 0; kk < 4; kk++) {
                uint32_t co = (uint32_t)(kk*16 + tig*2) * 2;
                uint32_t bh[2], bl[2];
                bh[0] = lds32(Khb + ro + co);
                bh[1] = lds32(Khb + ro + co + 16);
                bl[0] = lds32(Klb + ro + co);
                bl[1] = lds32(Klb + ro + co + 16);
                mma16816(sacc[nt], qh[kk], bh);
                mma16816(sacc[nt], qh[kk], bl);
                mma16816(sacc[nt], ql[kk], bh);
            }
        }

        // ---- online softmax (scale x8 folded into exp2 constant)
        float mx0 = -1e30f, mx1 = -1e30f;
        #pragma unroll
        for (int nt = 0; nt < 8; nt++) {
            mx0 = fmaxf(mx0, fmaxf(sacc[nt][0], sacc[nt][1]));
            mx1 = fmaxf(mx1, fmaxf(sacc[nt][2], sacc[nt][3]));
        }
        mx0 = fmaxf(mx0, __shfl_xor_sync(0xffffffffu, mx0, 1));
        mx0 = fmaxf(mx0, __shfl_xor_sync(0xffffffffu, mx0, 2));
        mx1 = fmaxf(mx1, __shfl_xor_sync(0xffffffffu, mx1, 1));
        mx1 = fmaxf(mx1, __shfl_xor_sync(0xffffffffu, mx1, 2));
        float nm0 = fmaxf(m0, mx0), nm1 = fmaxf(m1, mx1);
        float corr0 = exp2f((m0 - nm0) * SCLOG2);
        float corr1 = exp2f((m1 - nm1) * SCLOG2);
        m0 = nm0; m1 = nm1;
        float rs0 = 0.f, rs1 = 0.f;
        #pragma unroll
        for (int nt = 0; nt < 8; nt++) {
            sacc[nt][0] = exp2f((sacc[nt][0] - nm0) * SCLOG2);
            sacc[nt][1] = exp2f((sacc[nt][1] - nm0) * SCLOG2);
            sacc[nt][2] = exp2f((sacc[nt][2] - nm1) * SCLOG2);
            sacc[nt][3] = exp2f((sacc[nt][3] - nm1) * SCLOG2);
            rs0 += sacc[nt][0] + sacc[nt][1];
            rs1 += sacc[nt][2] + sacc[nt][3];
        }
        rs0 += __shfl_xor_sync(0xffffffffu, rs0, 1);
        rs0 += __shfl_xor_sync(0xffffffffu, rs0, 2);
        rs1 += __shfl_xor_sync(0xffffffffu, rs1, 1);
        rs1 += __shfl_xor_sync(0xffffffffu, rs1, 2);
        l0 = l0 * corr0 + rs0;
        l1 = l1 * corr1 + rs1;
        #pragma unroll
        for (int nt = 0; nt < 8; nt++) {
            oacc[nt][0] *= corr0; oacc[nt][1] *= corr0;
            oacc[nt][2] *= corr1; oacc[nt][3] *= corr1;
        }

        // ---- O += P V, P in registers (hi/lo), V from smem
        #pragma unroll
        for (int kblk = 0; kblk < 4; kblk++) {
            uint32_t ah[4], al[4];
            split2(sacc[2*kblk][0],   sacc[2*kblk][1],   ah[0], al[0]);
            split2(sacc[2*kblk][2],   sacc[2*kblk][3],   ah[1], al[1]);
            split2(sacc[2*kblk+1][0], sacc[2*kblk+1][1], ah[2], al[2]);
            split2(sacc[2*kblk+1][2], sacc[2*kblk+1][3], ah[3], al[3]);
            uint32_t co = (uint32_t)(kblk*16 + tig*2) * 2;
            #pragma unroll
            for (int nt = 0; nt < 8; nt++) {
                uint32_t ro = (uint32_t)((nt*8 + gid) * AKS) * 2;
                uint32_t bh[2], bl[2];
                bh[0] = lds32(Vhb + ro + co);
                bh[1] = lds32(Vhb + ro + co + 16);
                bl[0] = lds32(Vlb + ro + co);
                bl[1] = lds32(Vlb + ro + co + 16);
                mma16816(oacc[nt], ah, bh);
                mma16816(oacc[nt], ah, bl);
                mma16816(oacc[nt], al, bh);
            }
        }
        __syncthreads();
    }

    // ---- epilogue: ctx = O/l + maskV, stored bf16 hi/lo
    float inv0 = 1.0f / l0, inv1 = 1.0f / l1;
    int q_lo = q0 + gid;
    int q_hi = q_lo + 8;
    #pragma unroll
    for (int nt = 0; nt < 8; nt++) {
        int hs = nt*8 + tig*2;
        float mv0 = gMV[ph*HSZ + hs], mv1 = gMV[ph*HSZ + hs + 1];
        float v0 = oacc[nt][0]*inv0 + mv0, v1 = oacc[nt][1]*inv0 + mv1;
        float v2 = oacc[nt][2]*inv1 + mv0, v3 = oacc[nt][3]*inv1 + mv1;
        size_t o0 = ((size_t)p*NN + q_lo) * DD + h*HSZ + hs;
        size_t o1 = ((size_t)p*NN + q_hi) * DD + h*HSZ + hs;
        uint32_t whi, wlo;
        split2(v0, v1, whi, wlo);
        *(uint32_t*)&gCh[o0] = whi; *(uint32_t*)&gCl[o0] = wlo;
        split2(v2, v3, whi, wlo);
        *(uint32_t*)&gCh[o1] = whi; *(uint32_t*)&gCl[o1] = wlo;
    }
}

extern "C" void kernel_launch(void* const* d_in, const int* in_sizes, int n_in,
                              void* d_out, int out_size) {
    const float* X      = (const float*)d_in[0];
    const float* mask   = (const float*)d_in[1];
    const float* qkv_w  = (const float*)d_in[2];
    const float* qkv_b  = (const float*)d_in[3];
    const float* proj_w = (const float*)d_in[4];
    const float* proj_b = (const float*)d_in[5];
    float* out = (float*)d_out;

    cudaFuncSetAttribute(gemm_mma, cudaFuncAttributeMaxDynamicSharedMemorySize, GEMM_SMEM);
    cudaFuncSetAttribute(attn_mma, cudaFuncAttributeMaxDynamicSharedMemorySize, ATTN_SMEM);

    __nv_bfloat16 *xhi, *xlo, *wqh, *wql, *wph, *wpl;
    cudaGetSymbolAddress((void**)&xhi, gXhi);
    cudaGetSymbolAddress((void**)&xlo, gXlo);
    cudaGetSymbolAddress((void**)&wqh, gWqh);
    cudaGetSymbolAddress((void**)&wql, gWql);
    cudaGetSymbolAddress((void**)&wph, gWph);
    cudaGetSymbolAddress((void**)&wpl, gWpl);

    split_kernel<<<(PP*NN*DD/4 + 255)/256, 256>>>(X, xhi, xlo, PP*NN*DD/4);
    tsplit_kernel<<<dim3(3*DD/32, DD/32), dim3(32,8)>>>(qkv_w, wqh, wql, DD, 3*DD);
    tsplit_kernel<<<dim3(DD/32, DD/32), dim3(32,8)>>>(proj_w, wph, wpl, DD, DD);
    gemm_mma<<<dim3(3*DD/256, PP*NN/128), 512, GEMM_SMEM>>>(0, qkv_b, nullptr);
    maskv_kernel<<<PP*HH, 256>>>(mask);
    attn_mma<<<dim3(NN/256, HH, PP), 512, ATTN_SMEM>>>();
    gemm_mma<<<dim3(DD/256, PP*NN/128), 512, GEMM_SMEM>>>(1, proj_b, out);
}

// round 7
// speedup vs baseline: 2.5716x; 1.0484x over previous
#include <cuda_runtime.h>
#include <cuda_bf16.h>
#include <cstdint>

#define PP 8
#define NN 1024
#define DD 768
#define HH 12
#define HSZ 64
#define SCLOG2 11.5423594967f   // 8 * log2(e)

// ---- scratch (static) ----
__device__ float gMV[PP*HH*HSZ];
__device__ __nv_bfloat16 gXhi[PP*NN*DD];
__device__ __nv_bfloat16 gXlo[PP*NN*DD];
__device__ __nv_bfloat16 gWqh[3*DD*DD];
__device__ __nv_bfloat16 gWql[3*DD*DD];
__device__ __nv_bfloat16 gWph[DD*DD];
__device__ __nv_bfloat16 gWpl[DD*DD];
__device__ __nv_bfloat16 gCh[PP*NN*DD];
__device__ __nv_bfloat16 gCl[PP*NN*DD];
// attention operands, bf16 hi/lo. Q,K: [ph][n][hs]; V transposed: [ph][hs][n]
__device__ __nv_bfloat16 gQh[PP*HH*NN*HSZ];
__device__ __nv_bfloat16 gQl[PP*HH*NN*HSZ];
__device__ __nv_bfloat16 gKh[PP*HH*NN*HSZ];
__device__ __nv_bfloat16 gKl[PP*HH*NN*HSZ];
__device__ __nv_bfloat16 gVth[PP*HH*NN*HSZ];
__device__ __nv_bfloat16 gVtl[PP*HH*NN*HSZ];

// ================= helpers =================
__device__ __forceinline__ uint32_t smem_u32(const void* p) {
    uint32_t a;
    asm("{ .reg .u64 t; cvta.to.shared.u64 t, %1; cvt.u32.u64 %0, t; }" : "=r"(a) : "l"(p));
    return a;
}
__device__ __forceinline__ uint32_t lds32(uint32_t a) {
    uint32_t v;
    asm volatile("ld.shared.b32 %0, [%1];" : "=r"(v) : "r"(a));
    return v;
}
#define CP16(saddr, gptr) \
    asm volatile("cp.async.cg.shared.global [%0], [%1], 16;" :: "r"(saddr), "l"(gptr))
#define CP_COMMIT() asm volatile("cp.async.commit_group;" ::: "memory")
#define CP_WAIT1()  asm volatile("cp.async.wait_group 1;" ::: "memory")
#define CP_WAIT0()  asm volatile("cp.async.wait_group 0;" ::: "memory")

__device__ __forceinline__ void mma16816(float* c, const uint32_t* a, const uint32_t* b) {
    asm volatile("mma.sync.aligned.m16n8k16.row.col.f32.bf16.bf16.f32 "
                 "{%0,%1,%2,%3}, {%4,%5,%6,%7}, {%8,%9}, {%0,%1,%2,%3};"
                 : "+f"(c[0]), "+f"(c[1]), "+f"(c[2]), "+f"(c[3])
                 : "r"(a[0]), "r"(a[1]), "r"(a[2]), "r"(a[3]), "r"(b[0]), "r"(b[1]));
}
// pack two floats -> bf16x2 (v0 in low half)
__device__ __forceinline__ uint32_t pack2(float v0, float v1) {
    uint32_t r;
    asm("cvt.rn.bf16x2.f32 %0, %1, %2;" : "=r"(r) : "f"(v1), "f"(v0));
    return r;
}
// hi/lo split of a float pair into two bf16x2 words
__device__ __forceinline__ void split2(float v0, float v1, uint32_t& phi, uint32_t& plo) {
    phi = pack2(v0, v1);
    float h0 = __uint_as_float(phi << 16);
    float h1 = __uint_as_float(phi & 0xffff0000u);
    plo = pack2(v0 - h0, v1 - h1);
}

// ================= split / transpose-split =================
__global__ void split_kernel(const float* __restrict__ src,
                             __nv_bfloat16* __restrict__ hi,
                             __nv_bfloat16* __restrict__ lo, int n4) {
    int i = blockIdx.x * blockDim.x + threadIdx.x;
    if (i >= n4) return;
    float4 v = ((const float4*)src)[i];
    uint32_t h[2], l[2];
    split2(v.x, v.y, h[0], l[0]);
    split2(v.z, v.w, h[1], l[1]);
    ((uint2*)hi)[i] = make_uint2(h[0], h[1]);
    ((uint2*)lo)[i] = make_uint2(l[0], l[1]);
}

__global__ void tsplit_kernel(const float* __restrict__ W,
                              __nv_bfloat16* __restrict__ Th,
                              __nv_bfloat16* __restrict__ Tl, int K, int N) {
    __shared__ float t[32][33];
    int k0 = blockIdx.y * 32, n0 = blockIdx.x * 32;
    int tx = threadIdx.x, ty = threadIdx.y;
    #pragma unroll
    for (int i = 0; i < 4; i++)
        t[ty + 8*i][tx] = W[(size_t)(k0 + ty + 8*i) * N + n0 + tx];
    __syncthreads();
    #pragma unroll
    for (int i = 0; i < 4; i++) {
        float x = t[tx][ty + 8*i];
        __nv_bfloat16 h = __float2bfloat16_rn(x);
        __nv_bfloat16 l = __float2bfloat16_rn(x - __bfloat162float(h));
        size_t o = (size_t)(n0 + ty + 8*i) * K + k0 + tx;
        Th[o] = h; Tl[o] = l;
    }
}

// ================= bf16x3 GEMM via mma.sync =================
// CTA tile 128(m) x 256(n), 512 threads (16 warps = 4m x 4n, warp tile 32x64),
// K-chunk 64, double-buffered cp.async.
#define PADK 72
#define TILE_AE (128*PADK)
#define TILE_BE (256*PADK)
#define ABUF ((2*TILE_AE + 2*TILE_BE)*2)   // 110592 B per buffer
#define GEMM_SMEM (2*ABUF)                 // 221184 B

__global__ __launch_bounds__(512, 1) void gemm_mma(int mode,
                                                   const float* __restrict__ bias,
                                                   float* __restrict__ out) {
    extern __shared__ __align__(16) char smem[];
    uint32_t sb = smem_u32(smem);
    int tid = threadIdx.x, wid = tid >> 5, lane = tid & 31;
    int wm = wid & 3, wn = wid >> 2;
    int row0 = blockIdx.y * 128, col0 = blockIdx.x * 256;
    int gid = lane >> 2, tig = lane & 3;

    const __nv_bfloat16* Ah = mode ? gCh : gXhi;
    const __nv_bfloat16* Al = mode ? gCl : gXlo;
    const __nv_bfloat16* Bh = mode ? gWph : gWqh;
    const __nv_bfloat16* Bl = mode ? gWpl : gWql;

    float acc[2][8][4];
    #pragma unroll
    for (int i = 0; i < 2; i++)
        #pragma unroll
        for (int j = 0; j < 8; j++)
            #pragma unroll
            for (int q = 0; q < 4; q++) acc[i][j][q] = 0.f;

    auto fill = [&](int s, int c) {
        int k0 = c * 64;
        uint32_t sbase = sb + s * ABUF;
        // A: 128 rows x 8 chunks = 1024 cp16 per type
        #pragma unroll
        for (int j = 0; j < 2; j++) {
            int e = j * 512 + tid;
            int r = e >> 3, v = e & 7;
            uint32_t d = sbase + (uint32_t)(r * PADK + v * 8) * 2;
            size_t go = (size_t)(row0 + r) * DD + k0 + v * 8;
            CP16(d, Ah + go);
            CP16(d + TILE_AE*2, Al + go);
        }
        // B: 256 rows x 8 chunks = 2048 cp16 per type
        #pragma unroll
        for (int j = 0; j < 4; j++) {
            int e = j * 512 + tid;
            int r = e >> 3, v = e & 7;
            uint32_t d = sbase + 2*TILE_AE*2 + (uint32_t)(r * PADK + v * 8) * 2;
            size_t go = (size_t)(col0 + r) * DD + k0 + v * 8;
            CP16(d, Bh + go);
            CP16(d + TILE_BE*2, Bl + go);
        }
        CP_COMMIT();
    };

    fill(0, 0);
    for (int c = 0; c < 12; c++) {
        if (c < 11) fill((c + 1) & 1, c + 1);
        if (c < 11) CP_WAIT1(); else CP_WAIT0();
        __syncthreads();

        uint32_t base = sb + (c & 1) * ABUF;
        uint32_t Ahb = base, Alb = base + TILE_AE*2;
        uint32_t Bhb = base + 2*TILE_AE*2, Blb = Bhb + TILE_BE*2;

        #pragma unroll
        for (int ks = 0; ks < 4; ks++) {
            int kcol = ks * 16 + tig * 2;
            uint32_t ah[2][4], al[2][4];
            #pragma unroll
            for (int mt = 0; mt < 2; mt++) {
                int r = wm * 32 + mt * 16 + gid;
                uint32_t o = (uint32_t)(r * PADK + kcol) * 2;
                ah[mt][0] = lds32(Ahb + o);
                ah[mt][1] = lds32(Ahb + o + 8*PADK*2);
                ah[mt][2] = lds32(Ahb + o + 16);
                ah[mt][3] = lds32(Ahb + o + 8*PADK*2 + 16);
                al[mt][0] = lds32(Alb + o);
                al[mt][1] = lds32(Alb + o + 8*PADK*2);
                al[mt][2] = lds32(Alb + o + 16);
                al[mt][3] = lds32(Alb + o + 8*PADK*2 + 16);
            }
            #pragma unroll
            for (int half = 0; half < 2; half++) {
                uint32_t bh[4][2], bl[4][2];
                #pragma unroll
                for (int nt = 0; nt < 4; nt++) {
                    int n = wn * 64 + half * 32 + nt * 8 + gid;
                    uint32_t o = (uint32_t)(n * PADK + kcol) * 2;
                    bh[nt][0] = lds32(Bhb + o);
                    bh[nt][1] = lds32(Bhb + o + 16);
                    bl[nt][0] = lds32(Blb + o);
                    bl[nt][1] = lds32(Blb + o + 16);
                }
                #pragma unroll
                for (int mt = 0; mt < 2; mt++)
                    #pragma unroll
                    for (int nt = 0; nt < 4; nt++) {
                        float* cc = acc[mt][half * 4 + nt];
                        mma16816(cc, ah[mt], bh[nt]);
                        mma16816(cc, ah[mt], bl[nt]);
                        mma16816(cc, al[mt], bh[nt]);
                    }
            }
        }
        __syncthreads();
    }

    // ---- epilogue ----
    #pragma unroll
    for (int mt = 0; mt < 2; mt++) {
        int m_lo = row0 + wm * 32 + mt * 16 + gid;
        int m_hi = m_lo + 8;
        #pragma unroll
        for (int j = 0; j < 8; j++) {
            int nc = col0 + wn * 64 + (j >> 2) * 32 + (j & 3) * 8 + tig * 2;
            float b0 = bias[nc], b1 = bias[nc + 1];
            float* cc = acc[mt][j];
            float v0 = cc[0] + b0, v1 = cc[1] + b1;  // row m_lo
            float v2 = cc[2] + b0, v3 = cc[3] + b1;  // row m_hi
            if (mode == 0) {
                int which = (nc >= 2*DD) ? 2 : ((nc >= DD) ? 1 : 0);
                int rem = nc - which * DD;
                int h = rem >> 6, hs = rem & 63;
                int p0 = m_lo >> 10, n0 = m_lo & 1023;
                int p1 = m_hi >> 10, n1 = m_hi & 1023;
                int ph0 = p0 * HH + h, ph1 = p1 * HH + h;
                uint32_t whi, wlo;
                if (which == 2) {
                    size_t r0 = ((size_t)ph0 * HSZ + hs) * NN;
                    size_t r1 = ((size_t)ph1 * HSZ + hs) * NN;
                    split2(v0, v1, whi, wlo);
                    gVth[r0 + n0] = __ushort_as_bfloat16((unsigned short)(whi & 0xffff));
                    gVth[r0 + NN + n0] = __ushort_as_bfloat16((unsigned short)(whi >> 16));
                    gVtl[r0 + n0] = __ushort_as_bfloat16((unsigned short)(wlo & 0xffff));
                    gVtl[r0 + NN + n0] = __ushort_as_bfloat16((unsigned short)(wlo >> 16));
                    split2(v2, v3, whi, wlo);
                    gVth[r1 + n1] = __ushort_as_bfloat16((unsigned short)(whi & 0xffff));
                    gVth[r1 + NN + n1] = __ushort_as_bfloat16((unsigned short)(whi >> 16));
                    gVtl[r1 + n1] = __ushort_as_bfloat16((unsigned short)(wlo & 0xffff));
                    gVtl[r1 + NN + n1] = __ushort_as_bfloat16((unsigned short)(wlo >> 16));
                } else {
                    __nv_bfloat16* dh = which ? gKh : gQh;
                    __nv_bfloat16* dl = which ? gKl : gQl;
                    size_t o0 = (((size_t)ph0 << 10) + n0) * HSZ + hs;
                    size_t o1 = (((size_t)ph1 << 10) + n1) * HSZ + hs;
                    split2(v0, v1, whi, wlo);
                    *(uint32_t*)&dh[o0] = whi; *(uint32_t*)&dl[o0] = wlo;
                    split2(v2, v3, whi, wlo);
                    *(uint32_t*)&dh[o1] = whi; *(uint32_t*)&dl[o1] = wlo;
                }
            } else {
                *(float2*)&out[(size_t)m_lo * DD + nc] = make_float2(v0, v1);
                *(float2*)&out[(size_t)m_hi * DD + nc] = make_float2(v2, v3);
            }
        }
    }
}

// ================= post-softmax mask term =================
__global__ void maskv_kernel(const float* __restrict__ mask) {
    int ph = blockIdx.x;
    int p = ph / HH;
    int w = threadIdx.x >> 5, lane = threadIdx.x & 31;
    const float* mp = mask + (size_t)p * NN;
    #pragma unroll
    for (int i = 0; i < 8; i++) {
        int hs = w * 8 + i;
        const __nv_bfloat16* vh = gVth + ((size_t)ph * HSZ + hs) * NN;
        const __nv_bfloat16* vl = gVtl + ((size_t)ph * HSZ + hs) * NN;
        float acc = 0.f;
        for (int k = lane; k < NN; k += 32)
            acc += mp[k] * (__bfloat162float(vh[k]) + __bfloat162float(vl[k]));
        #pragma unroll
        for (int s = 16; s > 0; s >>= 1) acc += __shfl_xor_sync(0xffffffffu, acc, s);
        if (lane == 0) gMV[ph * HSZ + hs] = acc;
    }
}

// ================= flash attention via mma.sync (bf16x3) =================
// CTA = (p, h, 256 q-rows), 512 threads = 16 warps x 16 q-rows.
// Buffer = 128 keys processed as two 64-key passes (no barrier between passes).
// smem per buffer: Kh[128][72], Kl[128][72], Vth[64][136], Vtl[64][136]
#define AKS 72
#define VKS 136
#define KT_B (128*AKS*2)            // 18432 B
#define VT_B (64*VKS*2)             // 17408 B
#define ABUF_B (2*KT_B + 2*VT_B)    // 71680 B
#define ATTN_SMEM (2*ABUF_B)        // 143360 B

__global__ __launch_bounds__(512, 1) void attn_mma() {
    extern __shared__ __align__(16) char smem[];
    uint32_t sb = smem_u32(smem);
    int tid = threadIdx.x, wid = tid >> 5, lane = tid & 31;
    int gid = lane >> 2, tig = lane & 3;
    int qb = blockIdx.x, h = blockIdx.y, p = blockIdx.z;
    int ph = p * HH + h;
    int q0 = qb * 256 + wid * 16;    // warp's first q row

    // ---- preload Q fragments (hi/lo), warp rows q0 + {gid, gid+8}
    uint32_t qh[4][4], ql[4][4];
    {
        const __nv_bfloat16* base_h = gQh + ((size_t)ph * NN + q0) * HSZ;
        const __nv_bfloat16* base_l = gQl + ((size_t)ph * NN + q0) * HSZ;
        #pragma unroll
        for (int kk = 0; kk < 4; kk++) {
            int c = kk * 16 + tig * 2;
            qh[kk][0] = *(const uint32_t*)(base_h + (size_t)gid * HSZ + c);
            qh[kk][1] = *(const uint32_t*)(base_h + (size_t)(gid+8) * HSZ + c);
            qh[kk][2] = *(const uint32_t*)(base_h + (size_t)gid * HSZ + c + 8);
            qh[kk][3] = *(const uint32_t*)(base_h + (size_t)(gid+8) * HSZ + c + 8);
            ql[kk][0] = *(const uint32_t*)(base_l + (size_t)gid * HSZ + c);
            ql[kk][1] = *(const uint32_t*)(base_l + (size_t)(gid+8) * HSZ + c);
            ql[kk][2] = *(const uint32_t*)(base_l + (size_t)gid * HSZ + c + 8);
            ql[kk][3] = *(const uint32_t*)(base_l + (size_t)(gid+8) * HSZ + c + 8);
        }
    }

    float oacc[8][4];
    #pragma unroll
    for (int i = 0; i < 8; i++)
        #pragma unroll
        for (int j = 0; j < 4; j++) oacc[i][j] = 0.f;
    float m0 = -1e30f, m1 = -1e30f, l0 = 0.f, l1 = 0.f;

    const __nv_bfloat16* Kh_g = gKh + (size_t)ph * NN * HSZ;
    const __nv_bfloat16* Kl_g = gKl + (size_t)ph * NN * HSZ;
    const __nv_bfloat16* Vh_g = gVth + (size_t)ph * HSZ * NN;
    const __nv_bfloat16* Vl_g = gVtl + (size_t)ph * HSZ * NN;

    auto fill = [&](int s, int kb) {   // kb = 128-key block index (0..7)
        uint32_t base = sb + s * ABUF_B;
        // K tile: 128 keys x 64 hs (1024 x 16B chunks per type)
        #pragma unroll
        for (int j = 0; j < 2; j++) {
            int e = j * 512 + tid;
            int r = e >> 3, ch = e & 7;
            uint32_t d = base + (uint32_t)(r * AKS + ch * 8) * 2;
            const __nv_bfloat16* gh = Kh_g + (size_t)(kb*128 + r) * HSZ + ch * 8;
            const __nv_bfloat16* gl = Kl_g + (size_t)(kb*128 + r) * HSZ + ch * 8;
            CP16(d, gh);
            CP16(d + KT_B, gl);
        }
        // Vt tile: 64 hs x 128 keys (1024 x 16B chunks per type)
        #pragma unroll
        for (int j = 0; j < 2; j++) {
            int e = j * 512 + tid;
            int r = e >> 4, ch = e & 15;
            uint32_t d = base + 2*KT_B + (uint32_t)(r * VKS + ch * 8) * 2;
            const __nv_bfloat16* gh = Vh_g + (size_t)r * NN + kb*128 + ch * 8;
            const __nv_bfloat16* gl = Vl_g + (size_t)r * NN + kb*128 + ch * 8;
            CP16(d, gh);
            CP16(d + VT_B, gl);
        }
        CP_COMMIT();
    };

    fill(0, 0);
    for (int kb = 0; kb < 8; kb++) {
        if (kb < 7) fill((kb + 1) & 1, kb + 1);
        if (kb < 7) CP_WAIT1(); else CP_WAIT0();
        __syncthreads();

        uint32_t base = sb + (kb & 1) * ABUF_B;
        uint32_t Khb = base, Klb = base + KT_B;
        uint32_t Vhb = base + 2*KT_B, Vlb = Vhb + VT_B;

        #pragma unroll
        for (int pass = 0; pass < 2; pass++) {
            uint32_t kro = (uint32_t)(pass * 64 * AKS) * 2;   // K tile row offset
            uint32_t vco = (uint32_t)(pass * 64) * 2;         // Vt col offset

            // ---- S = Q K^T (16 x 64 per warp), 3-term hi/lo
            float sacc[8][4];
            #pragma unroll
            for (int nt = 0; nt < 8; nt++) {
                #pragma unroll
                for (int j = 0; j < 4; j++) sacc[nt][j] = 0.f;
                uint32_t ro = kro + (uint32_t)((nt*8 + gid) * AKS) * 2;
                #pragma unroll
                for (int kk = 0; kk < 4; kk++) {
                    uint32_t co = (uint32_t)(kk*16 + tig*2) * 2;
                    uint32_t bh[2], bl[2];
                    bh[0] = lds32(Khb + ro + co);
                    bh[1] = lds32(Khb + ro + co + 16);
                    bl[0] = lds32(Klb + ro + co);
                    bl[1] = lds32(Klb + ro + co + 16);
                    mma16816(sacc[nt], qh[kk], bh);
                    mma16816(sacc[nt], qh[kk], bl);
                    mma16816(sacc[nt], ql[kk], bh);
                }
            }

            // ---- online softmax
            float mx0 = -1e30f, mx1 = -1e30f;
            #pragma unroll
            for (int nt = 0; nt < 8; nt++) {
                mx0 = fmaxf(mx0, fmaxf(sacc[nt][0], sacc[nt][1]));
                mx1 = fmaxf(mx1, fmaxf(sacc[nt][2], sacc[nt][3]));
            }
            mx0 = fmaxf(mx0, __shfl_xor_sync(0xffffffffu, mx0, 1));
            mx0 = fmaxf(mx0, __shfl_xor_sync(0xffffffffu, mx0, 2));
            mx1 = fmaxf(mx1, __shfl_xor_sync(0xffffffffu, mx1, 1));
            mx1 = fmaxf(mx1, __shfl_xor_sync(0xffffffffu, mx1, 2));
            float nm0 = fmaxf(m0, mx0), nm1 = fmaxf(m1, mx1);
            float corr0 = exp2f((m0 - nm0) * SCLOG2);
            float corr1 = exp2f((m1 - nm1) * SCLOG2);
            m0 = nm0; m1 = nm1;
            float rs0 = 0.f, rs1 = 0.f;
            #pragma unroll
            for (int nt = 0; nt < 8; nt++) {
                sacc[nt][0] = exp2f((sacc[nt][0] - nm0) * SCLOG2);
                sacc[nt][1] = exp2f((sacc[nt][1] - nm0) * SCLOG2);
                sacc[nt][2] = exp2f((sacc[nt][2] - nm1) * SCLOG2);
                sacc[nt][3] = exp2f((sacc[nt][3] - nm1) * SCLOG2);
                rs0 += sacc[nt][0] + sacc[nt][1];
                rs1 += sacc[nt][2] + sacc[nt][3];
            }
            rs0 += __shfl_xor_sync(0xffffffffu, rs0, 1);
            rs0 += __shfl_xor_sync(0xffffffffu, rs0, 2);
            rs1 += __shfl_xor_sync(0xffffffffu, rs1, 1);
            rs1 += __shfl_xor_sync(0xffffffffu, rs1, 2);
            l0 = l0 * corr0 + rs0;
            l1 = l1 * corr1 + rs1;
            #pragma unroll
            for (int nt = 0; nt < 8; nt++) {
                oacc[nt][0] *= corr0; oacc[nt][1] *= corr0;
                oacc[nt][2] *= corr1; oacc[nt][3] *= corr1;
            }

            // ---- O += P V
            #pragma unroll
            for (int kblk = 0; kblk < 4; kblk++) {
                uint32_t ah[4], al[4];
                split2(sacc[2*kblk][0],   sacc[2*kblk][1],   ah[0], al[0]);
                split2(sacc[2*kblk][2],   sacc[2*kblk][3],   ah[1], al[1]);
                split2(sacc[2*kblk+1][0], sacc[2*kblk+1][1], ah[2], al[2]);
                split2(sacc[2*kblk+1][2], sacc[2*kblk+1][3], ah[3], al[3]);
                uint32_t co = vco + (uint32_t)(kblk*16 + tig*2) * 2;
                #pragma unroll
                for (int nt = 0; nt < 8; nt++) {
                    uint32_t ro = (uint32_t)((nt*8 + gid) * VKS) * 2;
                    uint32_t bh[2], bl[2];
                    bh[0] = lds32(Vhb + ro + co);
                    bh[1] = lds32(Vhb + ro + co + 16);
                    bl[0] = lds32(Vlb + ro + co);
                    bl[1] = lds32(Vlb + ro + co + 16);
                    mma16816(oacc[nt], ah, bh);
                    mma16816(oacc[nt], ah, bl);
                    mma16816(oacc[nt], al, bh);
                }
            }
        }
        __syncthreads();
    }

    // ---- epilogue: ctx = O/l + maskV, stored bf16 hi/lo
    float inv0 = 1.0f / l0, inv1 = 1.0f / l1;
    int q_lo = q0 + gid;
    int q_hi = q_lo + 8;
    #pragma unroll
    for (int nt = 0; nt < 8; nt++) {
        int hs = nt*8 + tig*2;
        float mv0 = gMV[ph*HSZ + hs], mv1 = gMV[ph*HSZ + hs + 1];
        float v0 = oacc[nt][0]*inv0 + mv0, v1 = oacc[nt][1]*inv0 + mv1;
        float v2 = oacc[nt][2]*inv1 + mv0, v3 = oacc[nt][3]*inv1 + mv1;
        size_t o0 = ((size_t)p*NN + q_lo) * DD + h*HSZ + hs;
        size_t o1 = ((size_t)p*NN + q_hi) * DD + h*HSZ + hs;
        uint32_t whi, wlo;
        split2(v0, v1, whi, wlo);
        *(uint32_t*)&gCh[o0] = whi; *(uint32_t*)&gCl[o0] = wlo;
        split2(v2, v3, whi, wlo);
        *(uint32_t*)&gCh[o1] = whi; *(uint32_t*)&gCl[o1] = wlo;
    }
}

extern "C" void kernel_launch(void* const* d_in, const int* in_sizes, int n_in,
                              void* d_out, int out_size) {
    const float* X      = (const float*)d_in[0];
    const float* mask   = (const float*)d_in[1];
    const float* qkv_w  = (const float*)d_in[2];
    const float* qkv_b  = (const float*)d_in[3];
    const float* proj_w = (const float*)d_in[4];
    const float* proj_b = (const float*)d_in[5];
    float* out = (float*)d_out;

    cudaFuncSetAttribute(gemm_mma, cudaFuncAttributeMaxDynamicSharedMemorySize, GEMM_SMEM);
    cudaFuncSetAttribute(attn_mma, cudaFuncAttributeMaxDynamicSharedMemorySize, ATTN_SMEM);

    __nv_bfloat16 *xhi, *xlo, *wqh, *wql, *wph, *wpl;
    cudaGetSymbolAddress((void**)&xhi, gXhi);
    cudaGetSymbolAddress((void**)&xlo, gXlo);
    cudaGetSymbolAddress((void**)&wqh, gWqh);
    cudaGetSymbolAddress((void**)&wql, gWql);
    cudaGetSymbolAddress((void**)&wph, gWph);
    cudaGetSymbolAddress((void**)&wpl, gWpl);

    split_kernel<<<(PP*NN*DD/4 + 255)/256, 256>>>(X, xhi, xlo, PP*NN*DD/4);
    tsplit_kernel<<<dim3(3*DD/32, DD/32), dim3(32,8)>>>(qkv_w, wqh, wql, DD, 3*DD);
    tsplit_kernel<<<dim3(DD/32, DD/32), dim3(32,8)>>>(proj_w, wph, wpl, DD, DD);
    gemm_mma<<<dim3(3*DD/256, PP*NN/128), 512, GEMM_SMEM>>>(0, qkv_b, nullptr);
    maskv_kernel<<<PP*HH, 256>>>(mask);
    attn_mma<<<dim3(NN/256, HH, PP), 512, ATTN_SMEM>>>();
    gemm_mma<<<dim3(DD/256, PP*NN/128), 512, GEMM_SMEM>>>(1, proj_b, out);
}